// round 11
// baseline (speedup 1.0000x reference)
#include <cuda_runtime.h>
#include <cuda_bf16.h>
#include <cstdint>
#include <cstddef>

#define N_PTS 524288
#define BB 2
#define FF 4
#define HH 64
#define WW 512
#define SS (BB*FF*HH*WW)
#define EPSBN 1e-5f

__device__ int   g_cnt[SS];
__device__ int   g_off[SS];
__device__ int   g_cursor[SS];
__device__ int   g_bsum[256];
__device__ int   g_boff[256];
__device__ float g_vsum[SS*3];
__device__ int   g_lin[N_PTS];
__device__ float g_feats[(size_t)N_PTS*8];
__device__ float g_y1[(size_t)N_PTS*64];
__device__ float g_y2[(size_t)N_PTS*128];
__device__ float g_y3[(size_t)N_PTS*256];
__device__ float g_y4[(size_t)N_PTS*256];
__device__ float g_comp[(size_t)SS*64];
__device__ float g_stat[4*512];
__device__ float g_scale[4*256];
__device__ float g_shift[4*256];
__device__ uint32_t g_w2h[4096],  g_w2l[4096];
__device__ uint32_t g_w3h[16384], g_w3l[16384];
__device__ uint32_t g_w4h[32768], g_w4l[32768];
__device__ uint32_t g_wch[8192],  g_wcl[8192];

__device__ __forceinline__ void split2(float x0, float x1, uint32_t& hi, uint32_t& lo){
    uint32_t h;
    asm("cvt.rn.bf16x2.f32 %0, %1, %2;" : "=r"(h) : "f"(x1), "f"(x0));
    float f0 = __uint_as_float(h << 16);
    float f1 = __uint_as_float(h & 0xFFFF0000u);
    float r0 = x0 - f0, r1 = x1 - f1;
    uint32_t l;
    asm("cvt.rn.bf16x2.f32 %0, %1, %2;" : "=r"(l) : "f"(r1), "f"(r0));
    hi = h; lo = l;
}
__device__ __forceinline__ void mma16(float* c, uint32_t a0, uint32_t a1, uint32_t a2, uint32_t a3,
                                      uint32_t b0, uint32_t b1){
    asm volatile(
        "mma.sync.aligned.m16n8k16.row.col.f32.bf16.bf16.f32 "
        "{%0,%1,%2,%3}, {%4,%5,%6,%7}, {%8,%9}, {%0,%1,%2,%3};"
        : "+f"(c[0]), "+f"(c[1]), "+f"(c[2]), "+f"(c[3])
        : "r"(a0), "r"(a1), "r"(a2), "r"(a3), "r"(b0), "r"(b1));
}
__device__ __forceinline__ void mma3(float* c, const uint4& aH, const uint4& aL,
                                     uint32_t bh0, uint32_t bh1, uint32_t bl0, uint32_t bl1){
    mma16(c, aH.x, aH.y, aH.z, aH.w, bh0, bh1);
    mma16(c, aH.x, aH.y, aH.z, aH.w, bl0, bl1);
    mma16(c, aL.x, aL.y, aL.z, aL.w, bh0, bh1);
}
__device__ __forceinline__ void cpa16(void* s, const void* g){
    uint32_t sa = (uint32_t)__cvta_generic_to_shared(s);
    asm volatile("cp.async.ca.shared.global [%0], [%1], 16;" :: "r"(sa), "l"(g) : "memory");
}
#define CP_COMMIT() asm volatile("cp.async.commit_group;" ::: "memory")
#define CP_WAIT0()  asm volatile("cp.async.wait_group 0;" ::: "memory")

__global__ void init_k(){
    long stride = (long)gridDim.x * blockDim.x;
    for (long i = (long)blockIdx.x*blockDim.x + threadIdx.x; i < (long)SS*3; i += stride){
        g_vsum[i] = 0.0f;
        if (i < SS) g_cnt[i] = 0;
        if (i < 4*512) g_stat[i] = 0.0f;
    }
}

__global__ __launch_bounds__(256) void scatter_k(const float* __restrict__ pts,
                                                 const int* __restrict__ coors){
    int i = blockIdx.x*blockDim.x + threadIdx.x;
    if (i >= N_PTS) return;
    int c0 = coors[4*i+0], c1 = coors[4*i+1], c2 = coors[4*i+2], c3 = coors[4*i+3];
    int l = ((c0*FF + c1)*HH + c2)*WW + c3;
    g_lin[i] = l;
    float4 p = *(const float4*)&pts[4*i];
    atomicAdd(&g_cnt[l], 1);
    atomicAdd(&g_vsum[3*l+0], p.x);
    atomicAdd(&g_vsum[3*l+1], p.y);
    atomicAdd(&g_vsum[3*l+2], p.z);
}

__global__ __launch_bounds__(1024) void scan1_k(){
    __shared__ int s[1024];
    int t = threadIdx.x, g = blockIdx.x*1024 + t;
    int v = g_cnt[g]; s[t] = v; __syncthreads();
    #pragma unroll
    for (int d = 1; d < 1024; d <<= 1){
        int x = (t >= d) ? s[t-d] : 0; __syncthreads();
        s[t] += x; __syncthreads();
    }
    g_off[g] = s[t] - v;
    if (t == 1023) g_bsum[blockIdx.x] = s[t];
}
__global__ void scan2_k(){
    __shared__ int s[256];
    int t = threadIdx.x;
    int v = g_bsum[t]; s[t] = v; __syncthreads();
    #pragma unroll
    for (int d = 1; d < 256; d <<= 1){
        int x = (t >= d) ? s[t-d] : 0; __syncthreads();
        s[t] += x; __syncthreads();
    }
    g_boff[t] = s[t] - v;
}
__global__ __launch_bounds__(1024) void scan3_k(){
    int g = blockIdx.x*1024 + threadIdx.x;
    int o = g_off[g] + g_boff[blockIdx.x];
    g_off[g] = o; g_cursor[g] = o;
}

__global__ __launch_bounds__(256) void csrfeats_k(const float* __restrict__ pts){
    __shared__ float st[16];
    int tid = threadIdx.x;
    if (tid < 16) st[tid] = 0.0f;
    __syncthreads();
    int i = blockIdx.x*256 + tid;
    int l = g_lin[i];
    int slot = atomicAdd(&g_cursor[l], 1);
    float4 p = *(const float4*)&pts[4*i];
    float inv = 1.0f / fmaxf((float)g_cnt[l], 1.0f);
    float mx = g_vsum[3*l+0]*inv, my = g_vsum[3*l+1]*inv, mz = g_vsum[3*l+2]*inv;
    float f[8];
    f[0]=p.x; f[1]=p.y; f[2]=p.z; f[3]=p.w;
    f[4]=sqrtf(p.x*p.x + p.y*p.y + p.z*p.z);
    f[5]=p.x-mx; f[6]=p.y-my; f[7]=p.z-mz;
    *(float4*)&g_feats[(size_t)slot*8]   = make_float4(f[0],f[1],f[2],f[3]);
    *(float4*)&g_feats[(size_t)slot*8+4] = make_float4(f[4],f[5],f[6],f[7]);
    #pragma unroll
    for (int ch = 0; ch < 8; ch++){
        float s = f[ch], q = f[ch]*f[ch];
        #pragma unroll
        for (int o = 16; o; o >>= 1){
            s += __shfl_xor_sync(0xFFFFFFFFu, s, o);
            q += __shfl_xor_sync(0xFFFFFFFFu, q, o);
        }
        if ((tid & 31) == 0){ atomicAdd(&st[ch], s); atomicAdd(&st[8+ch], q); }
    }
    __syncthreads();
    if (tid < 8)       atomicAdd(&g_stat[tid], st[tid]);
    else if (tid < 16) atomicAdd(&g_stat[256 + tid - 8], st[tid]);
}

__global__ void bnparam_k(const float* __restrict__ gam, const float* __restrict__ bet,
                          int C, int layer){
    int c = threadIdx.x;
    if (c < C){
        float n = (float)N_PTS;
        float m = g_stat[layer*512 + c] / n;
        float v = g_stat[layer*512 + 256 + c] / n - m*m;
        float sc = gam[c] / sqrtf(v + EPSBN);
        g_scale[layer*256+c] = sc;
        g_shift[layer*256+c] = bet[c] - m*sc;
    }
}

__global__ __launch_bounds__(256) void stats_k(const float* __restrict__ y){
    int tid = threadIdx.x;
    int c = tid & 63, rr = tid >> 6;
    float s = 0.0f, q = 0.0f;
    for (long row = (long)blockIdx.x*4 + rr; row < N_PTS; row += (long)gridDim.x*4){
        float v = y[row*64 + c];
        s += v; q += v*v;
    }
    __shared__ float sm[256];
    sm[tid] = s; __syncthreads();
    if (tid < 64){
        float t = sm[tid] + sm[tid+64] + sm[tid+128] + sm[tid+192];
        atomicAdd(&g_stat[512 + tid], t);
    }
    __syncthreads();
    sm[tid] = q; __syncthreads();
    if (tid < 64){
        float t = sm[tid] + sm[tid+64] + sm[tid+128] + sm[tid+192];
        atomicAdd(&g_stat[512 + 256 + tid], t);
    }
}

__global__ __launch_bounds__(128) void gemm1_k(const float* __restrict__ W1){
    __shared__ float Ws[8][64];
    __shared__ float sc[8], sh[8];
    int tid = threadIdx.x;
    for (int i = tid; i < 512; i += 128) Ws[i>>6][i&63] = W1[i];
    if (tid < 8){ sc[tid] = g_scale[tid]; sh[tid] = g_shift[tid]; }
    __syncthreads();
    int row = blockIdx.x*128 + tid;
    float4 fa = *(const float4*)&g_feats[(size_t)row*8];
    float4 fb = *(const float4*)&g_feats[(size_t)row*8+4];
    float f[8] = {fa.x,fa.y,fa.z,fa.w,fb.x,fb.y,fb.z,fb.w};
    #pragma unroll
    for (int k = 0; k < 8; k++) f[k] = f[k]*sc[k] + sh[k];
    #pragma unroll
    for (int c4 = 0; c4 < 16; c4++){
        float4 acc = make_float4(0,0,0,0);
        #pragma unroll
        for (int k = 0; k < 8; k++){
            float4 w = *(const float4*)&Ws[k][c4*4];
            acc.x += f[k]*w.x; acc.y += f[k]*w.y;
            acc.z += f[k]*w.z; acc.w += f[k]*w.w;
        }
        *(float4*)&g_y1[(size_t)row*64 + c4*4] = acc;
    }
}

__device__ __forceinline__ void tr_body(const float* __restrict__ W,
                                        uint32_t* __restrict__ Wh,
                                        uint32_t* __restrict__ Wl,
                                        int Kd, int Cd, int blk){
    int i = blk*256 + threadIdx.x;
    if (i >= Cd*Kd/2) return;
    int n = i / (Kd/2);
    int k = 2*(i % (Kd/2));
    int c = k >> 5, h = (k >> 4) & 1;
    int kp16 = (k >> 1) & 7;
    int q = kp16 & 3, rb = kp16 >> 2;
    int j = n >> 3, gr = n & 7;
    int jj = j >> 1, jpar = j & 1;
    int addr = c*(Cd*16) + (h*(Cd/16) + jj)*128 + (gr*4+q)*4 + jpar*2 + rb;
    uint32_t hi, lo;
    split2(W[(size_t)k*Cd + n], W[(size_t)(k+1)*Cd + n], hi, lo);
    Wh[addr] = hi; Wl[addr] = lo;
}
__global__ __launch_bounds__(256) void tr_all_k(const float* __restrict__ W2,
                                                const float* __restrict__ W3,
                                                const float* __restrict__ W4,
                                                const float* __restrict__ Wc){
    int b = blockIdx.x;
    if (b < 16)       tr_body(W2, g_w2h, g_w2l, 64, 128, b);
    else if (b < 80)  tr_body(W3, g_w3h, g_w3l, 128, 256, b-16);
    else if (b < 208) tr_body(W4, g_w4h, g_w4l, 256, 256, b-80);
    else              tr_body(Wc, g_wch, g_wcl, 256, 64, b-208);
}

// ---- bf16x3 GEMM: depth-2 A prefetch, double-buffered smem, cp.async B ----
template<int K, int COUT, bool ADD_BIAS, bool STATS>
__global__ __launch_bounds__(256) void mm_k(const float* __restrict__ A,
                                            const uint32_t* __restrict__ Bh,
                                            const uint32_t* __restrict__ Bl,
                                            float* __restrict__ Y,
                                            const float* __restrict__ bias,
                                            int layer, float* __restrict__ statp){
    constexpr int NC = K/32;
    constexpr int NCOL = COUT/128;
    extern __shared__ char smem[];
    uint32_t* Ah_s = (uint32_t*)smem;
    uint32_t* Al_s = Ah_s + 4096;
    uint32_t* Bh_s = Al_s + 4096;
    uint32_t* Bl_s = Bh_s + 4096*NCOL;
    float*    sstat = (float*)(Bl_s + 4096*NCOL);

    int tid = threadIdx.x, wid = tid >> 5, lane = tid & 31;
    int gr = lane >> 2, q = lane & 3;
    int row0 = blockIdx.x*128;
    int mw = wid & 3, nw = wid >> 2, fw = wid;
    int ar0 = row0 + 16*fw + gr;
    int b16 = tid >> 4, h_b = b16 >> 3, jj_b = b16 & 7, l16 = tid & 15;

    if (STATS){
        for (int i = tid; i < 2*COUT; i += 256) sstat[i] = 0.0f;
    }

    float acc[NCOL][2][8][4];
    #pragma unroll
    for (int ch = 0; ch < NCOL; ch++)
        #pragma unroll
        for (int i = 0; i < 2; i++)
            #pragma unroll
            for (int j = 0; j < 8; j++)
                #pragma unroll
                for (int cc = 0; cc < 4; cc++) acc[ch][i][j][cc] = 0.0f;

    const float* scp = &g_scale[layer*256];
    const float* shp = &g_shift[layer*256];

    // two register sets for depth-2 A prefetch
    float2 L[2][2][4];

    auto ldgA = [&](int set, int c){
        #pragma unroll
        for (int h = 0; h < 2; h++){
            const float* p0 = A + (size_t)ar0*K + c*32 + 16*h + 2*q;
            L[set][h][0] = *(const float2*)p0;
            L[set][h][1] = *(const float2*)(p0 + 8);
            const float* p1 = p0 + (size_t)8*K;
            L[set][h][2] = *(const float2*)p1;
            L[set][h][3] = *(const float2*)(p1 + 8);
        }
    };
    auto stsA = [&](int set, int c, int buf){
        #pragma unroll
        for (int h = 0; h < 2; h++){
            int kb = c*32 + 16*h + 2*q;
            float2 sA = *(const float2*)&scp[kb],   hA = *(const float2*)&shp[kb];
            float2 sB = *(const float2*)&scp[kb+8], hB = *(const float2*)&shp[kb+8];
            uint32_t r0h,r0l,r1h,r1l,r2h,r2l,r3h,r3l;
            split2(fmaxf(L[set][h][0].x*sA.x + hA.x, 0.0f), fmaxf(L[set][h][0].y*sA.y + hA.y, 0.0f), r0h, r0l);
            split2(fmaxf(L[set][h][2].x*sA.x + hA.x, 0.0f), fmaxf(L[set][h][2].y*sA.y + hA.y, 0.0f), r1h, r1l);
            split2(fmaxf(L[set][h][1].x*sB.x + hB.x, 0.0f), fmaxf(L[set][h][1].y*sB.y + hB.y, 0.0f), r2h, r2l);
            split2(fmaxf(L[set][h][3].x*sB.x + hB.x, 0.0f), fmaxf(L[set][h][3].y*sB.y + hB.y, 0.0f), r3h, r3l);
            uint32_t sb = (uint32_t)(buf*2048 + (h*8 + fw)*128 + lane*4);
            *(uint4*)&Ah_s[sb] = make_uint4(r0h,r1h,r2h,r3h);
            *(uint4*)&Al_s[sb] = make_uint4(r0l,r1l,r2l,r3l);
        }
    };
    auto cpB = [&](int c, int buf){
        #pragma unroll
        for (int ch = 0; ch < NCOL; ch++){
            size_t gb = (size_t)c*(COUT*16) + (size_t)(h_b*(COUT/16) + ch*8 + jj_b)*128 + l16*8;
            uint32_t sb = (uint32_t)(buf*2048*NCOL + ch*2048 + (h_b*8 + jj_b)*128 + l16*8);
            cpa16(&Bh_s[sb],   &Bh[gb]);
            cpa16(&Bh_s[sb+4], &Bh[gb+4]);
            cpa16(&Bl_s[sb],   &Bl[gb]);
            cpa16(&Bl_s[sb+4], &Bl[gb+4]);
        }
    };

    // prologue
    ldgA(0, 0);
    cpB(0, 0);
    CP_COMMIT();
    stsA(0, 0, 0);
    if (NC > 1) ldgA(1, 1);
    CP_WAIT0();
    __syncthreads();

    for (int c = 0; c < NC; c++){
        int par = c & 1, npar = par ^ 1;
        uint32_t aoff = (uint32_t)par*2048;
        uint32_t boff = (uint32_t)par*2048*NCOL;
        if (c+1 < NC){
            cpB(c+1, npar);
            CP_COMMIT();
        }
        if (c+2 < NC) ldgA(par, c+2);   // depth-2: overwrite the set consumed last iter
        #pragma unroll
        for (int h = 0; h < 2; h++){
            uint4 aH[2], aL[2];
            #pragma unroll
            for (int i = 0; i < 2; i++){
                uint32_t sb = aoff + (uint32_t)((h*8 + 2*mw + i)*128 + lane*4);
                aH[i] = *(const uint4*)&Ah_s[sb];
                aL[i] = *(const uint4*)&Al_s[sb];
            }
            #pragma unroll
            for (int ch = 0; ch < NCOL; ch++){
                #pragma unroll
                for (int half = 0; half < 2; half++){
                    int jj0 = nw*4 + half*2;
                    uint32_t base = boff + ch*2048 + (h*8 + jj0)*128 + lane*4;
                    uint4 bH0 = *(const uint4*)&Bh_s[base];
                    uint4 bH1 = *(const uint4*)&Bh_s[base + 128];
                    uint4 bL0 = *(const uint4*)&Bl_s[base];
                    uint4 bL1 = *(const uint4*)&Bl_s[base + 128];
                    #pragma unroll
                    for (int i = 0; i < 2; i++){
                        mma3(acc[ch][i][half*4+0], aH[i], aL[i], bH0.x, bH0.y, bL0.x, bL0.y);
                        mma3(acc[ch][i][half*4+1], aH[i], aL[i], bH0.z, bH0.w, bL0.z, bL0.w);
                        mma3(acc[ch][i][half*4+2], aH[i], aL[i], bH1.x, bH1.y, bL1.x, bL1.y);
                        mma3(acc[ch][i][half*4+3], aH[i], aL[i], bH1.z, bH1.w, bL1.z, bL1.w);
                    }
                }
            }
        }
        if (c+1 < NC){
            stsA(npar, c+1, npar);
            CP_WAIT0();
        }
        __syncthreads();
    }

    #pragma unroll
    for (int ch = 0; ch < NCOL; ch++){
        #pragma unroll
        for (int i = 0; i < 2; i++){
            #pragma unroll
            for (int j = 0; j < 8; j++){
                int col = ch*128 + nw*64 + j*8 + 2*q;
                int r   = row0 + mw*32 + i*16 + gr;
                float2 lo = make_float2(acc[ch][i][j][0], acc[ch][i][j][1]);
                float2 hi = make_float2(acc[ch][i][j][2], acc[ch][i][j][3]);
                if (ADD_BIAS){
                    float bx = bias[col], by = bias[col+1];
                    lo.x += bx; lo.y += by; hi.x += bx; hi.y += by;
                }
                *(float2*)&Y[(size_t)r*COUT + col]     = lo;
                *(float2*)&Y[(size_t)(r+8)*COUT + col] = hi;
            }
        }
    }
    if (STATS){
        #pragma unroll
        for (int ch = 0; ch < NCOL; ch++){
            #pragma unroll
            for (int j = 0; j < 8; j++){
                float se = acc[ch][0][j][0] + acc[ch][0][j][2] + acc[ch][1][j][0] + acc[ch][1][j][2];
                float so = acc[ch][0][j][1] + acc[ch][0][j][3] + acc[ch][1][j][1] + acc[ch][1][j][3];
                float qe = acc[ch][0][j][0]*acc[ch][0][j][0] + acc[ch][0][j][2]*acc[ch][0][j][2]
                         + acc[ch][1][j][0]*acc[ch][1][j][0] + acc[ch][1][j][2]*acc[ch][1][j][2];
                float qo = acc[ch][0][j][1]*acc[ch][0][j][1] + acc[ch][0][j][3]*acc[ch][0][j][3]
                         + acc[ch][1][j][1]*acc[ch][1][j][1] + acc[ch][1][j][3]*acc[ch][1][j][3];
                #pragma unroll
                for (int m = 4; m <= 16; m <<= 1){
                    se += __shfl_xor_sync(0xFFFFFFFFu, se, m);
                    so += __shfl_xor_sync(0xFFFFFFFFu, so, m);
                    qe += __shfl_xor_sync(0xFFFFFFFFu, qe, m);
                    qo += __shfl_xor_sync(0xFFFFFFFFu, qo, m);
                }
                if (lane < 4){
                    int col = ch*128 + nw*64 + j*8 + 2*q;
                    atomicAdd(&sstat[col],        se);
                    atomicAdd(&sstat[col+1],      so);
                    atomicAdd(&sstat[COUT+col],   qe);
                    atomicAdd(&sstat[COUT+col+1], qo);
                }
            }
        }
        __syncthreads();
        for (int i = tid; i < 2*COUT; i += 256){
            int c2 = (i < COUT) ? i : (i - COUT);
            atomicAdd(&statp[(i < COUT ? 0 : 256) + c2], sstat[i]);
        }
    }
}

// ---- voxel compress ----
__global__ __launch_bounds__(256) void comp_k(const float* __restrict__ bc){
    extern __shared__ char smem[];
    uint32_t* Bh_s = (uint32_t*)smem;
    uint32_t* Bl_s = Bh_s + 8192;
    uint32_t* Ah_s = Bl_s + 8192;
    uint32_t* Al_s = Ah_s + 4096;
    int* scnt = (int*)(Al_s + 4096);
    int* soff = scnt + 128;

    int tid = threadIdx.x, wid = tid >> 5, lane = tid & 31;
    int gr = lane >> 2, q = lane & 3;
    int row0 = blockIdx.x*128;
    int mw = wid & 3, nw = wid >> 2, fw = wid;

    for (int idx = tid*4; idx < 8192; idx += 1024){
        cpa16(&Bh_s[idx], &g_wch[idx]);
        cpa16(&Bl_s[idx], &g_wcl[idx]);
    }
    CP_COMMIT();
    if (tid < 128){ scnt[tid] = g_cnt[row0+tid]; soff[tid] = g_off[row0+tid]; }

    float acc[2][4][4];
    #pragma unroll
    for (int i = 0; i < 2; i++)
        #pragma unroll
        for (int j = 0; j < 4; j++)
            #pragma unroll
            for (int cc = 0; cc < 4; cc++) acc[i][j][cc] = 0.0f;

    CP_WAIT0();
    __syncthreads();

    int lv0 = 16*fw + gr, lv1 = lv0 + 8;
    int cnt0 = scnt[lv0], off0 = soff[lv0];
    int cnt1 = scnt[lv1], off1 = soff[lv1];

    float2 M0[4], M1[4];
    auto gather = [&](int c){
        int kbase = c*32 + 2*q;
        if (cnt0 <= 0){
            #pragma unroll
            for (int t = 0; t < 4; t++) M0[t] = make_float2(0,0);
        } else {
            const float* p = &g_y4[(size_t)off0*256 + kbase];
            M0[0]=*(const float2*)p; M0[1]=*(const float2*)(p+8);
            M0[2]=*(const float2*)(p+16); M0[3]=*(const float2*)(p+24);
            for (int jj = 1; jj < cnt0; jj++){
                const float* pj = p + (size_t)jj*256;
                float2 w;
                w=*(const float2*)pj;      M0[0].x=fmaxf(M0[0].x,w.x); M0[0].y=fmaxf(M0[0].y,w.y);
                w=*(const float2*)(pj+8);  M0[1].x=fmaxf(M0[1].x,w.x); M0[1].y=fmaxf(M0[1].y,w.y);
                w=*(const float2*)(pj+16); M0[2].x=fmaxf(M0[2].x,w.x); M0[2].y=fmaxf(M0[2].y,w.y);
                w=*(const float2*)(pj+24); M0[3].x=fmaxf(M0[3].x,w.x); M0[3].y=fmaxf(M0[3].y,w.y);
            }
        }
        if (cnt1 <= 0){
            #pragma unroll
            for (int t = 0; t < 4; t++) M1[t] = make_float2(0,0);
        } else {
            const float* p = &g_y4[(size_t)off1*256 + kbase];
            M1[0]=*(const float2*)p; M1[1]=*(const float2*)(p+8);
            M1[2]=*(const float2*)(p+16); M1[3]=*(const float2*)(p+24);
            for (int jj = 1; jj < cnt1; jj++){
                const float* pj = p + (size_t)jj*256;
                float2 w;
                w=*(const float2*)pj;      M1[0].x=fmaxf(M1[0].x,w.x); M1[0].y=fmaxf(M1[0].y,w.y);
                w=*(const float2*)(pj+8);  M1[1].x=fmaxf(M1[1].x,w.x); M1[1].y=fmaxf(M1[1].y,w.y);
                w=*(const float2*)(pj+16); M1[2].x=fmaxf(M1[2].x,w.x); M1[2].y=fmaxf(M1[2].y,w.y);
                w=*(const float2*)(pj+24); M1[3].x=fmaxf(M1[3].x,w.x); M1[3].y=fmaxf(M1[3].y,w.y);
            }
        }
    };
    auto storeA = [&](int buf){
        #pragma unroll
        for (int h = 0; h < 2; h++){
            uint32_t r0h,r0l,r1h,r1l,r2h,r2l,r3h,r3l;
            split2(M0[h*2+0].x, M0[h*2+0].y, r0h, r0l);
            split2(M1[h*2+0].x, M1[h*2+0].y, r1h, r1l);
            split2(M0[h*2+1].x, M0[h*2+1].y, r2h, r2l);
            split2(M1[h*2+1].x, M1[h*2+1].y, r3h, r3l);
            uint32_t sb = (uint32_t)(buf*2048 + (h*8 + fw)*128 + lane*4);
            *(uint4*)&Ah_s[sb] = make_uint4(r0h,r1h,r2h,r3h);
            *(uint4*)&Al_s[sb] = make_uint4(r0l,r1l,r2l,r3l);
        }
    };

    gather(0);
    storeA(0);
    __syncthreads();

    for (int c = 0; c < 8; c++){
        int buf = c & 1, nbuf = buf ^ 1;
        if (c+1 < 8) gather(c+1);
        uint32_t aoff = (uint32_t)buf*2048;
        #pragma unroll
        for (int h = 0; h < 2; h++){
            uint4 aH[2], aL[2];
            #pragma unroll
            for (int i = 0; i < 2; i++){
                uint32_t sb = aoff + (uint32_t)((h*8 + 2*mw + i)*128 + lane*4);
                aH[i] = *(const uint4*)&Ah_s[sb];
                aL[i] = *(const uint4*)&Al_s[sb];
            }
            int jj0 = nw*2;
            uint32_t base = (uint32_t)(c*1024 + (h*4 + jj0)*128 + lane*4);
            uint4 bH0 = *(const uint4*)&Bh_s[base];
            uint4 bH1 = *(const uint4*)&Bh_s[base + 128];
            uint4 bL0 = *(const uint4*)&Bl_s[base];
            uint4 bL1 = *(const uint4*)&Bl_s[base + 128];
            #pragma unroll
            for (int i = 0; i < 2; i++){
                mma3(acc[i][0], aH[i], aL[i], bH0.x, bH0.y, bL0.x, bL0.y);
                mma3(acc[i][1], aH[i], aL[i], bH0.z, bH0.w, bL0.z, bL0.w);
                mma3(acc[i][2], aH[i], aL[i], bH1.x, bH1.y, bL1.x, bL1.y);
                mma3(acc[i][3], aH[i], aL[i], bH1.z, bH1.w, bL1.z, bL1.w);
            }
        }
        if (c+1 < 8) storeA(nbuf);
        __syncthreads();
    }

    #pragma unroll
    for (int i = 0; i < 2; i++){
        #pragma unroll
        for (int j = 0; j < 4; j++){
            int cl = nw*32 + j*8 + 2*q;
            int r  = mw*32 + i*16 + gr;
            float m0 = (scnt[r]   > 0) ? 1.0f : 0.0f;
            float m1 = (scnt[r+8] > 0) ? 1.0f : 0.0f;
            float bx = bc[cl], by = bc[cl+1];
            float2 lo, hi;
            lo.x = fmaxf(acc[i][j][0] + bx, 0.0f)*m0;
            lo.y = fmaxf(acc[i][j][1] + by, 0.0f)*m0;
            hi.x = fmaxf(acc[i][j][2] + bx, 0.0f)*m1;
            hi.y = fmaxf(acc[i][j][3] + by, 0.0f)*m1;
            *(float2*)&g_comp[(size_t)(row0 + r)*64 + cl]     = lo;
            *(float2*)&g_comp[(size_t)(row0 + r + 8)*64 + cl] = hi;
        }
    }
}

__global__ __launch_bounds__(256) void residual_k(float* __restrict__ out){
    int idx = blockIdx.x*blockDim.x + threadIdx.x;
    const int TOT = BB*192*HH*WW;
    if (idx >= TOT) return;
    int w  = idx % WW;
    int h  = (idx / WW) % HH;
    int ch = (idx / (WW*HH)) % 192;
    int b  = idx / (WW*HH*192);
    int f = ch >> 6, j = ch & 63;
    int vl = ((b*FF + (FF-1))*HH + h)*WW + w;
    int vf = ((b*FF + f)*HH + h)*WW + w;
    out[idx] = g_comp[(size_t)vl*64 + j] - g_comp[(size_t)vf*64 + j];
}

extern "C" void kernel_launch(void* const* d_in, const int* in_sizes, int n_in,
                              void* d_out, int out_size){
    const float* pts   = (const float*)d_in[0];
    const int*   coors = (const int*)  d_in[1];
    const float* pre_g = (const float*)d_in[2];
    const float* pre_b = (const float*)d_in[3];
    const float* W1    = (const float*)d_in[4];
    const float* g1    = (const float*)d_in[5];
    const float* b1    = (const float*)d_in[6];
    const float* W2    = (const float*)d_in[7];
    const float* g2    = (const float*)d_in[8];
    const float* b2    = (const float*)d_in[9];
    const float* W3    = (const float*)d_in[10];
    const float* g3    = (const float*)d_in[11];
    const float* b3    = (const float*)d_in[12];
    const float* W4    = (const float*)d_in[13];
    const float* b4    = (const float*)d_in[14];
    const float* Wc    = (const float*)d_in[15];
    const float* bc    = (const float*)d_in[16];
    float* out = (float*)d_out;

    void *py1, *py2, *py3, *py4, *pstat;
    void *p2h,*p2l,*p3h,*p3l,*p4h,*p4l;
    cudaGetSymbolAddress(&py1, g_y1);
    cudaGetSymbolAddress(&py2, g_y2);
    cudaGetSymbolAddress(&py3, g_y3);
    cudaGetSymbolAddress(&py4, g_y4);
    cudaGetSymbolAddress(&pstat, g_stat);
    cudaGetSymbolAddress(&p2h, g_w2h); cudaGetSymbolAddress(&p2l, g_w2l);
    cudaGetSymbolAddress(&p3h, g_w3h); cudaGetSymbolAddress(&p3l, g_w3l);
    cudaGetSymbolAddress(&p4h, g_w4h); cudaGetSymbolAddress(&p4l, g_w4l);
    float* statb = (float*)pstat;

    const int SM_128 = 32768 + 32768 + 2*128*4;
    const int SM_256 = 32768 + 65536 + 2*256*4;
    const int SM_COMP = 65536 + 32768 + 2*128*4;
    static bool attr_set = false;
    if (!attr_set){
        cudaFuncSetAttribute(mm_k<64,128,false,true>,  cudaFuncAttributeMaxDynamicSharedMemorySize, SM_128);
        cudaFuncSetAttribute(mm_k<128,256,false,true>, cudaFuncAttributeMaxDynamicSharedMemorySize, SM_256);
        cudaFuncSetAttribute(mm_k<256,256,true,false>, cudaFuncAttributeMaxDynamicSharedMemorySize, SM_256);
        cudaFuncSetAttribute(comp_k, cudaFuncAttributeMaxDynamicSharedMemorySize, SM_COMP);
        attr_set = true;
    }

    init_k<<<1024, 256>>>();                // launch 0
    tr_all_k<<<240, 256>>>(W2, W3, W4, Wc); // launch 1
    scatter_k<<<N_PTS/256, 256>>>(pts, coors); // launch 2

    // launch 3 — PROBE: 1-wave clone of mm L4 for ncu (output overwritten by real L4)
    mm_k<256,256,true,false><<<148, 256, SM_256>>>(
        (const float*)py3, (const uint32_t*)p4h, (const uint32_t*)p4l,
        (float*)py4, b4, 3, nullptr);

    scan1_k<<<SS/1024, 1024>>>();
    scan2_k<<<1, 256>>>();
    scan3_k<<<SS/1024, 1024>>>();
    csrfeats_k<<<N_PTS/256, 256>>>(pts);
    bnparam_k<<<1, 256>>>(pre_g, pre_b, 8, 0);

    gemm1_k<<<N_PTS/128, 128>>>(W1);
    stats_k<<<2048, 256>>>((const float*)py1);
    bnparam_k<<<1, 256>>>(g1, b1, 64, 1);

    mm_k<64,128,false,true><<<N_PTS/128, 256, SM_128>>>(
        (const float*)py1, (const uint32_t*)p2h, (const uint32_t*)p2l,
        (float*)py2, nullptr, 1, statb + 2*512);
    bnparam_k<<<1, 256>>>(g2, b2, 128, 2);

    mm_k<128,256,false,true><<<N_PTS/128, 256, SM_256>>>(
        (const float*)py2, (const uint32_t*)p3h, (const uint32_t*)p3l,
        (float*)py3, nullptr, 2, statb + 3*512);
    bnparam_k<<<1, 256>>>(g3, b3, 256, 3);

    mm_k<256,256,true,false><<<N_PTS/128, 256, SM_256>>>(
        (const float*)py3, (const uint32_t*)p4h, (const uint32_t*)p4l,
        (float*)py4, b4, 3, nullptr);

    comp_k<<<SS/128, 256, SM_COMP>>>(bc);

    const int TOT = BB*192*HH*WW;
    residual_k<<<(TOT + 255)/256, 256>>>(out);

    (void)in_sizes; (void)n_in; (void)out_size;
}

// round 12
// speedup vs baseline: 1.1271x; 1.1271x over previous
#include <cuda_runtime.h>
#include <cuda_bf16.h>
#include <cstdint>
#include <cstddef>

#define N_PTS 524288
#define BB 2
#define FF 4
#define HH 64
#define WW 512
#define SS (BB*FF*HH*WW)
#define EPSBN 1e-5f

__device__ int   g_cnt[SS];
__device__ int   g_off[SS];
__device__ int   g_cursor[SS];
__device__ int   g_bsum[256];
__device__ int   g_boff[256];
__device__ float g_vsum[SS*3];
__device__ int   g_lin[N_PTS];
__device__ float g_feats[(size_t)N_PTS*8];
__device__ float g_y1[(size_t)N_PTS*64];
__device__ float g_y2[(size_t)N_PTS*128];
__device__ float g_y3[(size_t)N_PTS*256];
__device__ float g_y4[(size_t)N_PTS*256];
__device__ float g_comp[(size_t)SS*64];
__device__ float g_stat[4*512];
__device__ float g_scale[4*256];
__device__ float g_shift[4*256];
__device__ uint32_t g_w2h[4096],  g_w2l[4096];
__device__ uint32_t g_w3h[16384], g_w3l[16384];
__device__ uint32_t g_w4h[32768], g_w4l[32768];
__device__ uint32_t g_wch[8192],  g_wcl[8192];

__device__ __forceinline__ void split2(float x0, float x1, uint32_t& hi, uint32_t& lo){
    uint32_t h;
    asm("cvt.rn.bf16x2.f32 %0, %1, %2;" : "=r"(h) : "f"(x1), "f"(x0));
    float f0 = __uint_as_float(h << 16);
    float f1 = __uint_as_float(h & 0xFFFF0000u);
    float r0 = x0 - f0, r1 = x1 - f1;
    uint32_t l;
    asm("cvt.rn.bf16x2.f32 %0, %1, %2;" : "=r"(l) : "f"(r1), "f"(r0));
    hi = h; lo = l;
}
__device__ __forceinline__ void mma16(float* c, uint32_t a0, uint32_t a1, uint32_t a2, uint32_t a3,
                                      uint32_t b0, uint32_t b1){
    asm volatile(
        "mma.sync.aligned.m16n8k16.row.col.f32.bf16.bf16.f32 "
        "{%0,%1,%2,%3}, {%4,%5,%6,%7}, {%8,%9}, {%0,%1,%2,%3};"
        : "+f"(c[0]), "+f"(c[1]), "+f"(c[2]), "+f"(c[3])
        : "r"(a0), "r"(a1), "r"(a2), "r"(a3), "r"(b0), "r"(b1));
}
__device__ __forceinline__ void mma3(float* c, const uint4& aH, const uint4& aL,
                                     uint32_t bh0, uint32_t bh1, uint32_t bl0, uint32_t bl1){
    mma16(c, aH.x, aH.y, aH.z, aH.w, bh0, bh1);
    mma16(c, aH.x, aH.y, aH.z, aH.w, bl0, bl1);
    mma16(c, aL.x, aL.y, aL.z, aL.w, bh0, bh1);
}
__device__ __forceinline__ void cpa16(void* s, const void* g){
    uint32_t sa = (uint32_t)__cvta_generic_to_shared(s);
    asm volatile("cp.async.ca.shared.global [%0], [%1], 16;" :: "r"(sa), "l"(g) : "memory");
}
#define CP_COMMIT() asm volatile("cp.async.commit_group;" ::: "memory")
#define CP_WAIT0()  asm volatile("cp.async.wait_group 0;" ::: "memory")

__global__ void init_k(){
    long stride = (long)gridDim.x * blockDim.x;
    for (long i = (long)blockIdx.x*blockDim.x + threadIdx.x; i < (long)SS*3; i += stride){
        g_vsum[i] = 0.0f;
        if (i < SS) g_cnt[i] = 0;
        if (i < 4*512) g_stat[i] = 0.0f;
    }
}

__global__ __launch_bounds__(256) void scatter_k(const float* __restrict__ pts,
                                                 const int* __restrict__ coors){
    int i = blockIdx.x*blockDim.x + threadIdx.x;
    if (i >= N_PTS) return;
    int c0 = coors[4*i+0], c1 = coors[4*i+1], c2 = coors[4*i+2], c3 = coors[4*i+3];
    int l = ((c0*FF + c1)*HH + c2)*WW + c3;
    g_lin[i] = l;
    float4 p = *(const float4*)&pts[4*i];
    atomicAdd(&g_cnt[l], 1);
    atomicAdd(&g_vsum[3*l+0], p.x);
    atomicAdd(&g_vsum[3*l+1], p.y);
    atomicAdd(&g_vsum[3*l+2], p.z);
}

__global__ __launch_bounds__(1024) void scan1_k(){
    __shared__ int s[1024];
    int t = threadIdx.x, g = blockIdx.x*1024 + t;
    int v = g_cnt[g]; s[t] = v; __syncthreads();
    #pragma unroll
    for (int d = 1; d < 1024; d <<= 1){
        int x = (t >= d) ? s[t-d] : 0; __syncthreads();
        s[t] += x; __syncthreads();
    }
    g_off[g] = s[t] - v;
    if (t == 1023) g_bsum[blockIdx.x] = s[t];
}
__global__ void scan2_k(){
    __shared__ int s[256];
    int t = threadIdx.x;
    int v = g_bsum[t]; s[t] = v; __syncthreads();
    #pragma unroll
    for (int d = 1; d < 256; d <<= 1){
        int x = (t >= d) ? s[t-d] : 0; __syncthreads();
        s[t] += x; __syncthreads();
    }
    g_boff[t] = s[t] - v;
}
__global__ __launch_bounds__(1024) void scan3_k(){
    int g = blockIdx.x*1024 + threadIdx.x;
    int o = g_off[g] + g_boff[blockIdx.x];
    g_off[g] = o; g_cursor[g] = o;
}

__global__ __launch_bounds__(256) void csrfeats_k(const float* __restrict__ pts){
    __shared__ float st[16];
    int tid = threadIdx.x;
    if (tid < 16) st[tid] = 0.0f;
    __syncthreads();
    int i = blockIdx.x*256 + tid;
    int l = g_lin[i];
    int slot = atomicAdd(&g_cursor[l], 1);
    float4 p = *(const float4*)&pts[4*i];
    float inv = 1.0f / fmaxf((float)g_cnt[l], 1.0f);
    float mx = g_vsum[3*l+0]*inv, my = g_vsum[3*l+1]*inv, mz = g_vsum[3*l+2]*inv;
    float f[8];
    f[0]=p.x; f[1]=p.y; f[2]=p.z; f[3]=p.w;
    f[4]=sqrtf(p.x*p.x + p.y*p.y + p.z*p.z);
    f[5]=p.x-mx; f[6]=p.y-my; f[7]=p.z-mz;
    *(float4*)&g_feats[(size_t)slot*8]   = make_float4(f[0],f[1],f[2],f[3]);
    *(float4*)&g_feats[(size_t)slot*8+4] = make_float4(f[4],f[5],f[6],f[7]);
    #pragma unroll
    for (int ch = 0; ch < 8; ch++){
        float s = f[ch], q = f[ch]*f[ch];
        #pragma unroll
        for (int o = 16; o; o >>= 1){
            s += __shfl_xor_sync(0xFFFFFFFFu, s, o);
            q += __shfl_xor_sync(0xFFFFFFFFu, q, o);
        }
        if ((tid & 31) == 0){ atomicAdd(&st[ch], s); atomicAdd(&st[8+ch], q); }
    }
    __syncthreads();
    if (tid < 8)       atomicAdd(&g_stat[tid], st[tid]);
    else if (tid < 16) atomicAdd(&g_stat[256 + tid - 8], st[tid]);
}

__global__ void bnparam_k(const float* __restrict__ gam, const float* __restrict__ bet,
                          int C, int layer){
    int c = threadIdx.x;
    if (c < C){
        float n = (float)N_PTS;
        float m = g_stat[layer*512 + c] / n;
        float v = g_stat[layer*512 + 256 + c] / n - m*m;
        float sc = gam[c] / sqrtf(v + EPSBN);
        g_scale[layer*256+c] = sc;
        g_shift[layer*256+c] = bet[c] - m*sc;
    }
}

__global__ __launch_bounds__(256) void stats_k(const float* __restrict__ y){
    int tid = threadIdx.x;
    int c = tid & 63, rr = tid >> 6;
    float s = 0.0f, q = 0.0f;
    for (long row = (long)blockIdx.x*4 + rr; row < N_PTS; row += (long)gridDim.x*4){
        float v = y[row*64 + c];
        s += v; q += v*v;
    }
    __shared__ float sm[256];
    sm[tid] = s; __syncthreads();
    if (tid < 64){
        float t = sm[tid] + sm[tid+64] + sm[tid+128] + sm[tid+192];
        atomicAdd(&g_stat[512 + tid], t);
    }
    __syncthreads();
    sm[tid] = q; __syncthreads();
    if (tid < 64){
        float t = sm[tid] + sm[tid+64] + sm[tid+128] + sm[tid+192];
        atomicAdd(&g_stat[512 + 256 + tid], t);
    }
}

__global__ __launch_bounds__(128) void gemm1_k(const float* __restrict__ W1){
    __shared__ float Ws[8][64];
    __shared__ float sc[8], sh[8];
    int tid = threadIdx.x;
    for (int i = tid; i < 512; i += 128) Ws[i>>6][i&63] = W1[i];
    if (tid < 8){ sc[tid] = g_scale[tid]; sh[tid] = g_shift[tid]; }
    __syncthreads();
    int row = blockIdx.x*128 + tid;
    float4 fa = *(const float4*)&g_feats[(size_t)row*8];
    float4 fb = *(const float4*)&g_feats[(size_t)row*8+4];
    float f[8] = {fa.x,fa.y,fa.z,fa.w,fb.x,fb.y,fb.z,fb.w};
    #pragma unroll
    for (int k = 0; k < 8; k++) f[k] = f[k]*sc[k] + sh[k];
    #pragma unroll
    for (int c4 = 0; c4 < 16; c4++){
        float4 acc = make_float4(0,0,0,0);
        #pragma unroll
        for (int k = 0; k < 8; k++){
            float4 w = *(const float4*)&Ws[k][c4*4];
            acc.x += f[k]*w.x; acc.y += f[k]*w.y;
            acc.z += f[k]*w.z; acc.w += f[k]*w.w;
        }
        *(float4*)&g_y1[(size_t)row*64 + c4*4] = acc;
    }
}

__device__ __forceinline__ void tr_body(const float* __restrict__ W,
                                        uint32_t* __restrict__ Wh,
                                        uint32_t* __restrict__ Wl,
                                        int Kd, int Cd, int blk){
    int i = blk*256 + threadIdx.x;
    if (i >= Cd*Kd/2) return;
    int n = i / (Kd/2);
    int k = 2*(i % (Kd/2));
    int c = k >> 5, h = (k >> 4) & 1;
    int kp16 = (k >> 1) & 7;
    int q = kp16 & 3, rb = kp16 >> 2;
    int j = n >> 3, gr = n & 7;
    int jj = j >> 1, jpar = j & 1;
    int addr = c*(Cd*16) + (h*(Cd/16) + jj)*128 + (gr*4+q)*4 + jpar*2 + rb;
    uint32_t hi, lo;
    split2(W[(size_t)k*Cd + n], W[(size_t)(k+1)*Cd + n], hi, lo);
    Wh[addr] = hi; Wl[addr] = lo;
}
__global__ __launch_bounds__(256) void tr_all_k(const float* __restrict__ W2,
                                                const float* __restrict__ W3,
                                                const float* __restrict__ W4,
                                                const float* __restrict__ Wc){
    int b = blockIdx.x;
    if (b < 16)       tr_body(W2, g_w2h, g_w2l, 64, 128, b);
    else if (b < 80)  tr_body(W3, g_w3h, g_w3l, 128, 256, b-16);
    else if (b < 208) tr_body(W4, g_w4h, g_w4l, 256, 256, b-80);
    else              tr_body(Wc, g_wch, g_wcl, 256, 64, b-208);
}

// ---- bf16x3 GEMM: depth-2 A prefetch with STATIC buffer parity ----
template<int K, int COUT, bool ADD_BIAS, bool STATS>
__global__ __launch_bounds__(256) void mm_k(const float* __restrict__ A,
                                            const uint32_t* __restrict__ Bh,
                                            const uint32_t* __restrict__ Bl,
                                            float* __restrict__ Y,
                                            const float* __restrict__ bias,
                                            int layer, float* __restrict__ statp){
    constexpr int NC = K/32;          // always even (2, 4, 8)
    constexpr int NCOL = COUT/128;
    extern __shared__ char smem[];
    uint32_t* Ah_s = (uint32_t*)smem;
    uint32_t* Al_s = Ah_s + 4096;
    uint32_t* Bh_s = Al_s + 4096;
    uint32_t* Bl_s = Bh_s + 4096*NCOL;
    float*    sstat = (float*)(Bl_s + 4096*NCOL);

    int tid = threadIdx.x, wid = tid >> 5, lane = tid & 31;
    int gr = lane >> 2, q = lane & 3;
    int row0 = blockIdx.x*128;
    int mw = wid & 3, nw = wid >> 2, fw = wid;
    int ar0 = row0 + 16*fw + gr;
    int b16 = tid >> 4, h_b = b16 >> 3, jj_b = b16 & 7, l16 = tid & 15;

    if (STATS){
        for (int i = tid; i < 2*COUT; i += 256) sstat[i] = 0.0f;
    }

    float acc[NCOL][2][8][4];
    #pragma unroll
    for (int ch = 0; ch < NCOL; ch++)
        #pragma unroll
        for (int i = 0; i < 2; i++)
            #pragma unroll
            for (int j = 0; j < 8; j++)
                #pragma unroll
                for (int cc = 0; cc < 4; cc++) acc[ch][i][j][cc] = 0.0f;

    const float* scp = &g_scale[layer*256];
    const float* shp = &g_shift[layer*256];

    // two STATICALLY-named register sets (no dynamic indexing -> stays in regs)
    float2 L0[2][4], L1[2][4];

    auto ldgA = [&](float2 (&Ls)[2][4], int c){
        #pragma unroll
        for (int h = 0; h < 2; h++){
            const float* p0 = A + (size_t)ar0*K + c*32 + 16*h + 2*q;
            Ls[h][0] = *(const float2*)p0;
            Ls[h][1] = *(const float2*)(p0 + 8);
            const float* p1 = p0 + (size_t)8*K;
            Ls[h][2] = *(const float2*)p1;
            Ls[h][3] = *(const float2*)(p1 + 8);
        }
    };
    auto stsA = [&](float2 (&Ls)[2][4], int c, uint32_t buf){
        #pragma unroll
        for (int h = 0; h < 2; h++){
            int kb = c*32 + 16*h + 2*q;
            float2 sA = *(const float2*)&scp[kb],   hA = *(const float2*)&shp[kb];
            float2 sB = *(const float2*)&scp[kb+8], hB = *(const float2*)&shp[kb+8];
            uint32_t r0h,r0l,r1h,r1l,r2h,r2l,r3h,r3l;
            split2(fmaxf(Ls[h][0].x*sA.x + hA.x, 0.0f), fmaxf(Ls[h][0].y*sA.y + hA.y, 0.0f), r0h, r0l);
            split2(fmaxf(Ls[h][2].x*sA.x + hA.x, 0.0f), fmaxf(Ls[h][2].y*sA.y + hA.y, 0.0f), r1h, r1l);
            split2(fmaxf(Ls[h][1].x*sB.x + hB.x, 0.0f), fmaxf(Ls[h][1].y*sB.y + hB.y, 0.0f), r2h, r2l);
            split2(fmaxf(Ls[h][3].x*sB.x + hB.x, 0.0f), fmaxf(Ls[h][3].y*sB.y + hB.y, 0.0f), r3h, r3l);
            uint32_t sb = buf*2048u + (uint32_t)((h*8 + fw)*128 + lane*4);
            *(uint4*)&Ah_s[sb] = make_uint4(r0h,r1h,r2h,r3h);
            *(uint4*)&Al_s[sb] = make_uint4(r0l,r1l,r2l,r3l);
        }
    };
    auto cpB = [&](int c, uint32_t buf){
        #pragma unroll
        for (int ch = 0; ch < NCOL; ch++){
            size_t gb = (size_t)c*(COUT*16) + (size_t)(h_b*(COUT/16) + ch*8 + jj_b)*128 + l16*8;
            uint32_t sb = buf*2048u*NCOL + (uint32_t)(ch*2048 + (h_b*8 + jj_b)*128 + l16*8);
            cpa16(&Bh_s[sb],   &Bh[gb]);
            cpa16(&Bh_s[sb+4], &Bh[gb+4]);
            cpa16(&Bl_s[sb],   &Bl[gb]);
            cpa16(&Bl_s[sb+4], &Bl[gb+4]);
        }
    };
    auto domma = [&](uint32_t buf){
        uint32_t aoff = buf*2048u;
        uint32_t boff = buf*2048u*NCOL;
        #pragma unroll
        for (int h = 0; h < 2; h++){
            uint4 aH[2], aL[2];
            #pragma unroll
            for (int i = 0; i < 2; i++){
                uint32_t sb = aoff + (uint32_t)((h*8 + 2*mw + i)*128 + lane*4);
                aH[i] = *(const uint4*)&Ah_s[sb];
                aL[i] = *(const uint4*)&Al_s[sb];
            }
            #pragma unroll
            for (int ch = 0; ch < NCOL; ch++){
                #pragma unroll
                for (int half = 0; half < 2; half++){
                    int jj0 = nw*4 + half*2;
                    uint32_t base = boff + ch*2048 + (h*8 + jj0)*128 + lane*4;
                    uint4 bH0 = *(const uint4*)&Bh_s[base];
                    uint4 bH1 = *(const uint4*)&Bh_s[base + 128];
                    uint4 bL0 = *(const uint4*)&Bl_s[base];
                    uint4 bL1 = *(const uint4*)&Bl_s[base + 128];
                    #pragma unroll
                    for (int i = 0; i < 2; i++){
                        mma3(acc[ch][i][half*4+0], aH[i], aL[i], bH0.x, bH0.y, bL0.x, bL0.y);
                        mma3(acc[ch][i][half*4+1], aH[i], aL[i], bH0.z, bH0.w, bL0.z, bL0.w);
                        mma3(acc[ch][i][half*4+2], aH[i], aL[i], bH1.x, bH1.y, bL1.x, bL1.y);
                        mma3(acc[ch][i][half*4+3], aH[i], aL[i], bH1.z, bH1.w, bL1.z, bL1.w);
                    }
                }
            }
        }
    };

    // prologue
    ldgA(L0, 0);
    cpB(0, 0); CP_COMMIT();
    stsA(L0, 0, 0);
    if (NC > 1) ldgA(L1, 1);
    CP_WAIT0();
    __syncthreads();

    #pragma unroll
    for (int cb = 0; cb < NC; cb += 2){
        { // even chunk: buffer 0; L0 free, L1 holds A(cb+1)
            int c = cb;
            if (c+1 < NC){ cpB(c+1, 1); CP_COMMIT(); }
            if (c+2 < NC) ldgA(L0, c+2);
            domma(0);
            if (c+1 < NC){ stsA(L1, c+1, 1); CP_WAIT0(); }
            __syncthreads();
        }
        if (cb+1 < NC){ // odd chunk: buffer 1; L1 free, L0 holds A(cb+2)
            int c = cb+1;
            if (c+1 < NC){ cpB(c+1, 0); CP_COMMIT(); }
            if (c+2 < NC) ldgA(L1, c+2);
            domma(1);
            if (c+1 < NC){ stsA(L0, c+1, 0); CP_WAIT0(); }
            __syncthreads();
        }
    }

    #pragma unroll
    for (int ch = 0; ch < NCOL; ch++){
        #pragma unroll
        for (int i = 0; i < 2; i++){
            #pragma unroll
            for (int j = 0; j < 8; j++){
                int col = ch*128 + nw*64 + j*8 + 2*q;
                int r   = row0 + mw*32 + i*16 + gr;
                float2 lo = make_float2(acc[ch][i][j][0], acc[ch][i][j][1]);
                float2 hi = make_float2(acc[ch][i][j][2], acc[ch][i][j][3]);
                if (ADD_BIAS){
                    float bx = bias[col], by = bias[col+1];
                    lo.x += bx; lo.y += by; hi.x += bx; hi.y += by;
                }
                *(float2*)&Y[(size_t)r*COUT + col]     = lo;
                *(float2*)&Y[(size_t)(r+8)*COUT + col] = hi;
            }
        }
    }
    if (STATS){
        #pragma unroll
        for (int ch = 0; ch < NCOL; ch++){
            #pragma unroll
            for (int j = 0; j < 8; j++){
                float se = acc[ch][0][j][0] + acc[ch][0][j][2] + acc[ch][1][j][0] + acc[ch][1][j][2];
                float so = acc[ch][0][j][1] + acc[ch][0][j][3] + acc[ch][1][j][1] + acc[ch][1][j][3];
                float qe = acc[ch][0][j][0]*acc[ch][0][j][0] + acc[ch][0][j][2]*acc[ch][0][j][2]
                         + acc[ch][1][j][0]*acc[ch][1][j][0] + acc[ch][1][j][2]*acc[ch][1][j][2];
                float qo = acc[ch][0][j][1]*acc[ch][0][j][1] + acc[ch][0][j][3]*acc[ch][0][j][3]
                         + acc[ch][1][j][1]*acc[ch][1][j][1] + acc[ch][1][j][3]*acc[ch][1][j][3];
                #pragma unroll
                for (int m = 4; m <= 16; m <<= 1){
                    se += __shfl_xor_sync(0xFFFFFFFFu, se, m);
                    so += __shfl_xor_sync(0xFFFFFFFFu, so, m);
                    qe += __shfl_xor_sync(0xFFFFFFFFu, qe, m);
                    qo += __shfl_xor_sync(0xFFFFFFFFu, qo, m);
                }
                if (lane < 4){
                    int col = ch*128 + nw*64 + j*8 + 2*q;
                    atomicAdd(&sstat[col],        se);
                    atomicAdd(&sstat[col+1],      so);
                    atomicAdd(&sstat[COUT+col],   qe);
                    atomicAdd(&sstat[COUT+col+1], qo);
                }
            }
        }
        __syncthreads();
        for (int i = tid; i < 2*COUT; i += 256){
            int c2 = (i < COUT) ? i : (i - COUT);
            atomicAdd(&statp[(i < COUT ? 0 : 256) + c2], sstat[i]);
        }
    }
}

// ---- voxel compress ----
__global__ __launch_bounds__(256) void comp_k(const float* __restrict__ bc){
    extern __shared__ char smem[];
    uint32_t* Bh_s = (uint32_t*)smem;
    uint32_t* Bl_s = Bh_s + 8192;
    uint32_t* Ah_s = Bl_s + 8192;
    uint32_t* Al_s = Ah_s + 4096;
    int* scnt = (int*)(Al_s + 4096);
    int* soff = scnt + 128;

    int tid = threadIdx.x, wid = tid >> 5, lane = tid & 31;
    int gr = lane >> 2, q = lane & 3;
    int row0 = blockIdx.x*128;
    int mw = wid & 3, nw = wid >> 2, fw = wid;

    for (int idx = tid*4; idx < 8192; idx += 1024){
        cpa16(&Bh_s[idx], &g_wch[idx]);
        cpa16(&Bl_s[idx], &g_wcl[idx]);
    }
    CP_COMMIT();
    if (tid < 128){ scnt[tid] = g_cnt[row0+tid]; soff[tid] = g_off[row0+tid]; }

    float acc[2][4][4];
    #pragma unroll
    for (int i = 0; i < 2; i++)
        #pragma unroll
        for (int j = 0; j < 4; j++)
            #pragma unroll
            for (int cc = 0; cc < 4; cc++) acc[i][j][cc] = 0.0f;

    CP_WAIT0();
    __syncthreads();

    int lv0 = 16*fw + gr, lv1 = lv0 + 8;
    int cnt0 = scnt[lv0], off0 = soff[lv0];
    int cnt1 = scnt[lv1], off1 = soff[lv1];

    float2 M0[4], M1[4];
    auto gather = [&](int c){
        int kbase = c*32 + 2*q;
        if (cnt0 <= 0){
            #pragma unroll
            for (int t = 0; t < 4; t++) M0[t] = make_float2(0,0);
        } else {
            const float* p = &g_y4[(size_t)off0*256 + kbase];
            M0[0]=*(const float2*)p; M0[1]=*(const float2*)(p+8);
            M0[2]=*(const float2*)(p+16); M0[3]=*(const float2*)(p+24);
            for (int jj = 1; jj < cnt0; jj++){
                const float* pj = p + (size_t)jj*256;
                float2 w;
                w=*(const float2*)pj;      M0[0].x=fmaxf(M0[0].x,w.x); M0[0].y=fmaxf(M0[0].y,w.y);
                w=*(const float2*)(pj+8);  M0[1].x=fmaxf(M0[1].x,w.x); M0[1].y=fmaxf(M0[1].y,w.y);
                w=*(const float2*)(pj+16); M0[2].x=fmaxf(M0[2].x,w.x); M0[2].y=fmaxf(M0[2].y,w.y);
                w=*(const float2*)(pj+24); M0[3].x=fmaxf(M0[3].x,w.x); M0[3].y=fmaxf(M0[3].y,w.y);
            }
        }
        if (cnt1 <= 0){
            #pragma unroll
            for (int t = 0; t < 4; t++) M1[t] = make_float2(0,0);
        } else {
            const float* p = &g_y4[(size_t)off1*256 + kbase];
            M1[0]=*(const float2*)p; M1[1]=*(const float2*)(p+8);
            M1[2]=*(const float2*)(p+16); M1[3]=*(const float2*)(p+24);
            for (int jj = 1; jj < cnt1; jj++){
                const float* pj = p + (size_t)jj*256;
                float2 w;
                w=*(const float2*)pj;      M1[0].x=fmaxf(M1[0].x,w.x); M1[0].y=fmaxf(M1[0].y,w.y);
                w=*(const float2*)(pj+8);  M1[1].x=fmaxf(M1[1].x,w.x); M1[1].y=fmaxf(M1[1].y,w.y);
                w=*(const float2*)(pj+16); M1[2].x=fmaxf(M1[2].x,w.x); M1[2].y=fmaxf(M1[2].y,w.y);
                w=*(const float2*)(pj+24); M1[3].x=fmaxf(M1[3].x,w.x); M1[3].y=fmaxf(M1[3].y,w.y);
            }
        }
    };
    auto storeA = [&](uint32_t buf){
        #pragma unroll
        for (int h = 0; h < 2; h++){
            uint32_t r0h,r0l,r1h,r1l,r2h,r2l,r3h,r3l;
            split2(M0[h*2+0].x, M0[h*2+0].y, r0h, r0l);
            split2(M1[h*2+0].x, M1[h*2+0].y, r1h, r1l);
            split2(M0[h*2+1].x, M0[h*2+1].y, r2h, r2l);
            split2(M1[h*2+1].x, M1[h*2+1].y, r3h, r3l);
            uint32_t sb = buf*2048u + (uint32_t)((h*8 + fw)*128 + lane*4);
            *(uint4*)&Ah_s[sb] = make_uint4(r0h,r1h,r2h,r3h);
            *(uint4*)&Al_s[sb] = make_uint4(r0l,r1l,r2l,r3l);
        }
    };

    gather(0);
    storeA(0);
    __syncthreads();

    for (int c = 0; c < 8; c++){
        int buf = c & 1, nbuf = buf ^ 1;
        if (c+1 < 8) gather(c+1);
        uint32_t aoff = (uint32_t)buf*2048;
        #pragma unroll
        for (int h = 0; h < 2; h++){
            uint4 aH[2], aL[2];
            #pragma unroll
            for (int i = 0; i < 2; i++){
                uint32_t sb = aoff + (uint32_t)((h*8 + 2*mw + i)*128 + lane*4);
                aH[i] = *(const uint4*)&Ah_s[sb];
                aL[i] = *(const uint4*)&Al_s[sb];
            }
            int jj0 = nw*2;
            uint32_t base = (uint32_t)(c*1024 + (h*4 + jj0)*128 + lane*4);
            uint4 bH0 = *(const uint4*)&Bh_s[base];
            uint4 bH1 = *(const uint4*)&Bh_s[base + 128];
            uint4 bL0 = *(const uint4*)&Bl_s[base];
            uint4 bL1 = *(const uint4*)&Bl_s[base + 128];
            #pragma unroll
            for (int i = 0; i < 2; i++){
                mma3(acc[i][0], aH[i], aL[i], bH0.x, bH0.y, bL0.x, bL0.y);
                mma3(acc[i][1], aH[i], aL[i], bH0.z, bH0.w, bL0.z, bL0.w);
                mma3(acc[i][2], aH[i], aL[i], bH1.x, bH1.y, bL1.x, bL1.y);
                mma3(acc[i][3], aH[i], aL[i], bH1.z, bH1.w, bL1.z, bL1.w);
            }
        }
        if (c+1 < 8) storeA((uint32_t)nbuf);
        __syncthreads();
    }

    #pragma unroll
    for (int i = 0; i < 2; i++){
        #pragma unroll
        for (int j = 0; j < 4; j++){
            int cl = nw*32 + j*8 + 2*q;
            int r  = mw*32 + i*16 + gr;
            float m0 = (scnt[r]   > 0) ? 1.0f : 0.0f;
            float m1 = (scnt[r+8] > 0) ? 1.0f : 0.0f;
            float bx = bc[cl], by = bc[cl+1];
            float2 lo, hi;
            lo.x = fmaxf(acc[i][j][0] + bx, 0.0f)*m0;
            lo.y = fmaxf(acc[i][j][1] + by, 0.0f)*m0;
            hi.x = fmaxf(acc[i][j][2] + bx, 0.0f)*m1;
            hi.y = fmaxf(acc[i][j][3] + by, 0.0f)*m1;
            *(float2*)&g_comp[(size_t)(row0 + r)*64 + cl]     = lo;
            *(float2*)&g_comp[(size_t)(row0 + r + 8)*64 + cl] = hi;
        }
    }
}

__global__ __launch_bounds__(256) void residual_k(float* __restrict__ out){
    int idx = blockIdx.x*blockDim.x + threadIdx.x;
    const int TOT = BB*192*HH*WW;
    if (idx >= TOT) return;
    int w  = idx % WW;
    int h  = (idx / WW) % HH;
    int ch = (idx / (WW*HH)) % 192;
    int b  = idx / (WW*HH*192);
    int f = ch >> 6, j = ch & 63;
    int vl = ((b*FF + (FF-1))*HH + h)*WW + w;
    int vf = ((b*FF + f)*HH + h)*WW + w;
    out[idx] = g_comp[(size_t)vl*64 + j] - g_comp[(size_t)vf*64 + j];
}

extern "C" void kernel_launch(void* const* d_in, const int* in_sizes, int n_in,
                              void* d_out, int out_size){
    const float* pts   = (const float*)d_in[0];
    const int*   coors = (const int*)  d_in[1];
    const float* pre_g = (const float*)d_in[2];
    const float* pre_b = (const float*)d_in[3];
    const float* W1    = (const float*)d_in[4];
    const float* g1    = (const float*)d_in[5];
    const float* b1    = (const float*)d_in[6];
    const float* W2    = (const float*)d_in[7];
    const float* g2    = (const float*)d_in[8];
    const float* b2    = (const float*)d_in[9];
    const float* W3    = (const float*)d_in[10];
    const float* g3    = (const float*)d_in[11];
    const float* b3    = (const float*)d_in[12];
    const float* W4    = (const float*)d_in[13];
    const float* b4    = (const float*)d_in[14];
    const float* Wc    = (const float*)d_in[15];
    const float* bc    = (const float*)d_in[16];
    float* out = (float*)d_out;

    void *py1, *py2, *py3, *py4, *pstat;
    void *p2h,*p2l,*p3h,*p3l,*p4h,*p4l;
    cudaGetSymbolAddress(&py1, g_y1);
    cudaGetSymbolAddress(&py2, g_y2);
    cudaGetSymbolAddress(&py3, g_y3);
    cudaGetSymbolAddress(&py4, g_y4);
    cudaGetSymbolAddress(&pstat, g_stat);
    cudaGetSymbolAddress(&p2h, g_w2h); cudaGetSymbolAddress(&p2l, g_w2l);
    cudaGetSymbolAddress(&p3h, g_w3h); cudaGetSymbolAddress(&p3l, g_w3l);
    cudaGetSymbolAddress(&p4h, g_w4h); cudaGetSymbolAddress(&p4l, g_w4l);
    float* statb = (float*)pstat;

    const int SM_128 = 32768 + 32768 + 2*128*4;
    const int SM_256 = 32768 + 65536 + 2*256*4;
    const int SM_COMP = 65536 + 32768 + 2*128*4;
    static bool attr_set = false;
    if (!attr_set){
        cudaFuncSetAttribute(mm_k<64,128,false,true>,  cudaFuncAttributeMaxDynamicSharedMemorySize, SM_128);
        cudaFuncSetAttribute(mm_k<128,256,false,true>, cudaFuncAttributeMaxDynamicSharedMemorySize, SM_256);
        cudaFuncSetAttribute(mm_k<256,256,true,false>, cudaFuncAttributeMaxDynamicSharedMemorySize, SM_256);
        cudaFuncSetAttribute(comp_k, cudaFuncAttributeMaxDynamicSharedMemorySize, SM_COMP);
        attr_set = true;
    }

    init_k<<<1024, 256>>>();                // launch 0
    tr_all_k<<<240, 256>>>(W2, W3, W4, Wc); // launch 1
    scatter_k<<<N_PTS/256, 256>>>(pts, coors); // launch 2

    // launch 3 — PROBE: 1-wave clone of mm L4 for ncu (output overwritten by real L4)
    mm_k<256,256,true,false><<<148, 256, SM_256>>>(
        (const float*)py3, (const uint32_t*)p4h, (const uint32_t*)p4l,
        (float*)py4, b4, 3, nullptr);

    scan1_k<<<SS/1024, 1024>>>();
    scan2_k<<<1, 256>>>();
    scan3_k<<<SS/1024, 1024>>>();
    csrfeats_k<<<N_PTS/256, 256>>>(pts);
    bnparam_k<<<1, 256>>>(pre_g, pre_b, 8, 0);

    gemm1_k<<<N_PTS/128, 128>>>(W1);
    stats_k<<<2048, 256>>>((const float*)py1);
    bnparam_k<<<1, 256>>>(g1, b1, 64, 1);

    mm_k<64,128,false,true><<<N_PTS/128, 256, SM_128>>>(
        (const float*)py1, (const uint32_t*)p2h, (const uint32_t*)p2l,
        (float*)py2, nullptr, 1, statb + 2*512);
    bnparam_k<<<1, 256>>>(g2, b2, 128, 2);

    mm_k<128,256,false,true><<<N_PTS/128, 256, SM_256>>>(
        (const float*)py2, (const uint32_t*)p3h, (const uint32_t*)p3l,
        (float*)py3, nullptr, 2, statb + 3*512);
    bnparam_k<<<1, 256>>>(g3, b3, 256, 3);

    mm_k<256,256,true,false><<<N_PTS/128, 256, SM_256>>>(
        (const float*)py3, (const uint32_t*)p4h, (const uint32_t*)p4l,
        (float*)py4, b4, 3, nullptr);

    comp_k<<<SS/128, 256, SM_COMP>>>(bc);

    const int TOT = BB*192*HH*WW;
    residual_k<<<(TOT + 255)/256, 256>>>(out);

    (void)in_sizes; (void)n_in; (void)out_size;
}

// round 13
// speedup vs baseline: 1.1484x; 1.0189x over previous
#include <cuda_runtime.h>
#include <cuda_bf16.h>
#include <cstdint>
#include <cstddef>

#define N_PTS 524288
#define BB 2
#define FF 4
#define HH 64
#define WW 512
#define SS (BB*FF*HH*WW)
#define EPSBN 1e-5f

__device__ int   g_cnt[SS];
__device__ int   g_off[SS];
__device__ int   g_cursor[SS];
__device__ int   g_bsum[256];
__device__ int   g_boff[256];
__device__ float g_vsum[SS*3];
__device__ int   g_lin[N_PTS];
__device__ float g_feats[(size_t)N_PTS*8];
__device__ float g_y1[(size_t)N_PTS*64];
__device__ float g_y2[(size_t)N_PTS*128];
__device__ float g_y3[(size_t)N_PTS*256];
__device__ float g_y4[(size_t)N_PTS*256];
__device__ float g_comp[(size_t)SS*64];
__device__ float g_stat[4*512];
__device__ float g_scale[4*256];
__device__ float g_shift[4*256];
__device__ uint32_t g_w2h[4096],  g_w2l[4096];
__device__ uint32_t g_w3h[16384], g_w3l[16384];
__device__ uint32_t g_w4h[32768], g_w4l[32768];
__device__ uint32_t g_wch[8192],  g_wcl[8192];

__device__ __forceinline__ void split2(float x0, float x1, uint32_t& hi, uint32_t& lo){
    uint32_t h;
    asm("cvt.rn.bf16x2.f32 %0, %1, %2;" : "=r"(h) : "f"(x1), "f"(x0));
    float f0 = __uint_as_float(h << 16);
    float f1 = __uint_as_float(h & 0xFFFF0000u);
    float r0 = x0 - f0, r1 = x1 - f1;
    uint32_t l;
    asm("cvt.rn.bf16x2.f32 %0, %1, %2;" : "=r"(l) : "f"(r1), "f"(r0));
    hi = h; lo = l;
}
__device__ __forceinline__ void mma16(float* c, uint32_t a0, uint32_t a1, uint32_t a2, uint32_t a3,
                                      uint32_t b0, uint32_t b1){
    asm volatile(
        "mma.sync.aligned.m16n8k16.row.col.f32.bf16.bf16.f32 "
        "{%0,%1,%2,%3}, {%4,%5,%6,%7}, {%8,%9}, {%0,%1,%2,%3};"
        : "+f"(c[0]), "+f"(c[1]), "+f"(c[2]), "+f"(c[3])
        : "r"(a0), "r"(a1), "r"(a2), "r"(a3), "r"(b0), "r"(b1));
}
__device__ __forceinline__ void mma3(float* c, const uint4& aH, const uint4& aL,
                                     uint32_t bh0, uint32_t bh1, uint32_t bl0, uint32_t bl1){
    mma16(c, aH.x, aH.y, aH.z, aH.w, bh0, bh1);
    mma16(c, aH.x, aH.y, aH.z, aH.w, bl0, bl1);
    mma16(c, aL.x, aL.y, aL.z, aL.w, bh0, bh1);
}
__device__ __forceinline__ void cpa16(void* s, const void* g){
    uint32_t sa = (uint32_t)__cvta_generic_to_shared(s);
    asm volatile("cp.async.ca.shared.global [%0], [%1], 16;" :: "r"(sa), "l"(g) : "memory");
}
#define CP_COMMIT() asm volatile("cp.async.commit_group;" ::: "memory")
#define CP_WAIT0()  asm volatile("cp.async.wait_group 0;" ::: "memory")

__global__ void init_k(){
    long stride = (long)gridDim.x * blockDim.x;
    for (long i = (long)blockIdx.x*blockDim.x + threadIdx.x; i < (long)SS*3; i += stride){
        g_vsum[i] = 0.0f;
        if (i < SS) g_cnt[i] = 0;
        if (i < 4*512) g_stat[i] = 0.0f;
    }
}

__global__ __launch_bounds__(256) void scatter_k(const float* __restrict__ pts,
                                                 const int* __restrict__ coors){
    int i = blockIdx.x*blockDim.x + threadIdx.x;
    if (i >= N_PTS) return;
    int c0 = coors[4*i+0], c1 = coors[4*i+1], c2 = coors[4*i+2], c3 = coors[4*i+3];
    int l = ((c0*FF + c1)*HH + c2)*WW + c3;
    g_lin[i] = l;
    float4 p = *(const float4*)&pts[4*i];
    atomicAdd(&g_cnt[l], 1);
    atomicAdd(&g_vsum[3*l+0], p.x);
    atomicAdd(&g_vsum[3*l+1], p.y);
    atomicAdd(&g_vsum[3*l+2], p.z);
}

__global__ __launch_bounds__(1024) void scan1_k(){
    __shared__ int s[1024];
    int t = threadIdx.x, g = blockIdx.x*1024 + t;
    int v = g_cnt[g]; s[t] = v; __syncthreads();
    #pragma unroll
    for (int d = 1; d < 1024; d <<= 1){
        int x = (t >= d) ? s[t-d] : 0; __syncthreads();
        s[t] += x; __syncthreads();
    }
    g_off[g] = s[t] - v;
    if (t == 1023) g_bsum[blockIdx.x] = s[t];
}
__global__ void scan2_k(){
    __shared__ int s[256];
    int t = threadIdx.x;
    int v = g_bsum[t]; s[t] = v; __syncthreads();
    #pragma unroll
    for (int d = 1; d < 256; d <<= 1){
        int x = (t >= d) ? s[t-d] : 0; __syncthreads();
        s[t] += x; __syncthreads();
    }
    g_boff[t] = s[t] - v;
}
__global__ __launch_bounds__(1024) void scan3_k(){
    int g = blockIdx.x*1024 + threadIdx.x;
    int o = g_off[g] + g_boff[blockIdx.x];
    g_off[g] = o; g_cursor[g] = o;
}

__global__ __launch_bounds__(256) void csrfeats_k(const float* __restrict__ pts){
    __shared__ float st[16];
    int tid = threadIdx.x;
    if (tid < 16) st[tid] = 0.0f;
    __syncthreads();
    int i = blockIdx.x*256 + tid;
    int l = g_lin[i];
    int slot = atomicAdd(&g_cursor[l], 1);
    float4 p = *(const float4*)&pts[4*i];
    float inv = 1.0f / fmaxf((float)g_cnt[l], 1.0f);
    float mx = g_vsum[3*l+0]*inv, my = g_vsum[3*l+1]*inv, mz = g_vsum[3*l+2]*inv;
    float f[8];
    f[0]=p.x; f[1]=p.y; f[2]=p.z; f[3]=p.w;
    f[4]=sqrtf(p.x*p.x + p.y*p.y + p.z*p.z);
    f[5]=p.x-mx; f[6]=p.y-my; f[7]=p.z-mz;
    *(float4*)&g_feats[(size_t)slot*8]   = make_float4(f[0],f[1],f[2],f[3]);
    *(float4*)&g_feats[(size_t)slot*8+4] = make_float4(f[4],f[5],f[6],f[7]);
    #pragma unroll
    for (int ch = 0; ch < 8; ch++){
        float s = f[ch], q = f[ch]*f[ch];
        #pragma unroll
        for (int o = 16; o; o >>= 1){
            s += __shfl_xor_sync(0xFFFFFFFFu, s, o);
            q += __shfl_xor_sync(0xFFFFFFFFu, q, o);
        }
        if ((tid & 31) == 0){ atomicAdd(&st[ch], s); atomicAdd(&st[8+ch], q); }
    }
    __syncthreads();
    if (tid < 8)       atomicAdd(&g_stat[tid], st[tid]);
    else if (tid < 16) atomicAdd(&g_stat[256 + tid - 8], st[tid]);
}

__global__ void bnparam_k(const float* __restrict__ gam, const float* __restrict__ bet,
                          int C, int layer){
    int c = threadIdx.x;
    if (c < C){
        float n = (float)N_PTS;
        float m = g_stat[layer*512 + c] / n;
        float v = g_stat[layer*512 + 256 + c] / n - m*m;
        float sc = gam[c] / sqrtf(v + EPSBN);
        g_scale[layer*256+c] = sc;
        g_shift[layer*256+c] = bet[c] - m*sc;
    }
}

__global__ __launch_bounds__(256) void stats_k(const float* __restrict__ y){
    int tid = threadIdx.x;
    int c = tid & 63, rr = tid >> 6;
    float s = 0.0f, q = 0.0f;
    for (long row = (long)blockIdx.x*4 + rr; row < N_PTS; row += (long)gridDim.x*4){
        float v = y[row*64 + c];
        s += v; q += v*v;
    }
    __shared__ float sm[256];
    sm[tid] = s; __syncthreads();
    if (tid < 64){
        float t = sm[tid] + sm[tid+64] + sm[tid+128] + sm[tid+192];
        atomicAdd(&g_stat[512 + tid], t);
    }
    __syncthreads();
    sm[tid] = q; __syncthreads();
    if (tid < 64){
        float t = sm[tid] + sm[tid+64] + sm[tid+128] + sm[tid+192];
        atomicAdd(&g_stat[512 + 256 + tid], t);
    }
}

__global__ __launch_bounds__(128) void gemm1_k(const float* __restrict__ W1){
    __shared__ float Ws[8][64];
    __shared__ float sc[8], sh[8];
    int tid = threadIdx.x;
    for (int i = tid; i < 512; i += 128) Ws[i>>6][i&63] = W1[i];
    if (tid < 8){ sc[tid] = g_scale[tid]; sh[tid] = g_shift[tid]; }
    __syncthreads();
    int row = blockIdx.x*128 + tid;
    float4 fa = *(const float4*)&g_feats[(size_t)row*8];
    float4 fb = *(const float4*)&g_feats[(size_t)row*8+4];
    float f[8] = {fa.x,fa.y,fa.z,fa.w,fb.x,fb.y,fb.z,fb.w};
    #pragma unroll
    for (int k = 0; k < 8; k++) f[k] = f[k]*sc[k] + sh[k];
    #pragma unroll
    for (int c4 = 0; c4 < 16; c4++){
        float4 acc = make_float4(0,0,0,0);
        #pragma unroll
        for (int k = 0; k < 8; k++){
            float4 w = *(const float4*)&Ws[k][c4*4];
            acc.x += f[k]*w.x; acc.y += f[k]*w.y;
            acc.z += f[k]*w.z; acc.w += f[k]*w.w;
        }
        *(float4*)&g_y1[(size_t)row*64 + c4*4] = acc;
    }
}

__device__ __forceinline__ void tr_body(const float* __restrict__ W,
                                        uint32_t* __restrict__ Wh,
                                        uint32_t* __restrict__ Wl,
                                        int Kd, int Cd, int blk){
    int i = blk*256 + threadIdx.x;
    if (i >= Cd*Kd/2) return;
    int n = i / (Kd/2);
    int k = 2*(i % (Kd/2));
    int c = k >> 5, h = (k >> 4) & 1;
    int kp16 = (k >> 1) & 7;
    int q = kp16 & 3, rb = kp16 >> 2;
    int j = n >> 3, gr = n & 7;
    int jj = j >> 1, jpar = j & 1;
    int addr = c*(Cd*16) + (h*(Cd/16) + jj)*128 + (gr*4+q)*4 + jpar*2 + rb;
    uint32_t hi, lo;
    split2(W[(size_t)k*Cd + n], W[(size_t)(k+1)*Cd + n], hi, lo);
    Wh[addr] = hi; Wl[addr] = lo;
}
__global__ __launch_bounds__(256) void tr_all_k(const float* __restrict__ W2,
                                                const float* __restrict__ W3,
                                                const float* __restrict__ W4,
                                                const float* __restrict__ Wc){
    int b = blockIdx.x;
    if (b < 16)       tr_body(W2, g_w2h, g_w2l, 64, 128, b);
    else if (b < 80)  tr_body(W3, g_w3h, g_w3l, 128, 256, b-16);
    else if (b < 208) tr_body(W4, g_w4h, g_w4l, 256, 256, b-80);
    else              tr_body(Wc, g_wch, g_wcl, 256, 64, b-208);
}

// ---- bf16x3 GEMM: resident Bh, streamed Bl, depth-2 A prefetch, static parity ----
template<int K, int COUT, bool ADD_BIAS, bool STATS>
__global__ __launch_bounds__(256) void mm_k(const float* __restrict__ A,
                                            const uint32_t* __restrict__ Bh,
                                            const uint32_t* __restrict__ Bl,
                                            float* __restrict__ Y,
                                            const float* __restrict__ bias,
                                            int layer, float* __restrict__ statp){
    constexpr int NC = K/32;           // even: 2, 4, 8
    constexpr int CW = COUT*16;        // words per chunk of B (one matrix)
    extern __shared__ char smem[];
    uint32_t* Ah_s = (uint32_t*)smem;            // [2][2048]
    uint32_t* Al_s = Ah_s + 4096;                // [2][2048]
    uint32_t* Blb  = Al_s + 4096;                // [2][CW]  streamed lo
    uint32_t* Bh_r = Blb + 2*CW;                 // [NC*CW]  resident hi
    float*    sstat = (float*)(Bh_r + NC*CW);

    int tid = threadIdx.x, wid = tid >> 5, lane = tid & 31;
    int gr = lane >> 2, q = lane & 3;
    int row0 = blockIdx.x*128;
    int mw = wid & 3, nw = wid >> 2, fw = wid;
    int ar0 = row0 + 16*fw + gr;
    int b16 = tid >> 4, h_b = b16 >> 3, jj_b = b16 & 7, l16 = tid & 15;

    if (STATS){
        for (int i = tid; i < 2*COUT; i += 256) sstat[i] = 0.0f;
    }

    float acc[COUT/128][2][8][4];
    #pragma unroll
    for (int ch = 0; ch < COUT/128; ch++)
        #pragma unroll
        for (int i = 0; i < 2; i++)
            #pragma unroll
            for (int j = 0; j < 8; j++)
                #pragma unroll
                for (int cc = 0; cc < 4; cc++) acc[ch][i][j][cc] = 0.0f;

    const float* scp = &g_scale[layer*256];
    const float* shp = &g_shift[layer*256];

    float2 L0[2][4], L1[2][4];

    auto ldgA = [&](float2 (&Ls)[2][4], int c){
        #pragma unroll
        for (int h = 0; h < 2; h++){
            const float* p0 = A + (size_t)ar0*K + c*32 + 16*h + 2*q;
            Ls[h][0] = *(const float2*)p0;
            Ls[h][1] = *(const float2*)(p0 + 8);
            const float* p1 = p0 + (size_t)8*K;
            Ls[h][2] = *(const float2*)p1;
            Ls[h][3] = *(const float2*)(p1 + 8);
        }
    };
    auto stsA = [&](float2 (&Ls)[2][4], int c, uint32_t buf){
        #pragma unroll
        for (int h = 0; h < 2; h++){
            int kb = c*32 + 16*h + 2*q;
            float2 sA = *(const float2*)&scp[kb],   hA = *(const float2*)&shp[kb];
            float2 sB = *(const float2*)&scp[kb+8], hB = *(const float2*)&shp[kb+8];
            uint32_t r0h,r0l,r1h,r1l,r2h,r2l,r3h,r3l;
            split2(fmaxf(Ls[h][0].x*sA.x + hA.x, 0.0f), fmaxf(Ls[h][0].y*sA.y + hA.y, 0.0f), r0h, r0l);
            split2(fmaxf(Ls[h][2].x*sA.x + hA.x, 0.0f), fmaxf(Ls[h][2].y*sA.y + hA.y, 0.0f), r1h, r1l);
            split2(fmaxf(Ls[h][1].x*sB.x + hB.x, 0.0f), fmaxf(Ls[h][1].y*sB.y + hB.y, 0.0f), r2h, r2l);
            split2(fmaxf(Ls[h][3].x*sB.x + hB.x, 0.0f), fmaxf(Ls[h][3].y*sB.y + hB.y, 0.0f), r3h, r3l);
            uint32_t sb = buf*2048u + (uint32_t)((h*8 + fw)*128 + lane*4);
            *(uint4*)&Ah_s[sb] = make_uint4(r0h,r1h,r2h,r3h);
            *(uint4*)&Al_s[sb] = make_uint4(r0l,r1l,r2l,r3l);
        }
    };
    auto cpBl = [&](int c, uint32_t buf){
        // global-internal layout kept: (h*(COUT/16) + j16)*128 slices
        #pragma unroll
        for (int rep = 0; rep < COUT/128; rep++){
            uint32_t off = (uint32_t)((h_b*(COUT/16) + rep*8 + jj_b)*128 + l16*8);
            size_t gb = (size_t)c*CW + off;
            uint32_t sb = buf*(uint32_t)CW + off;
            cpa16(&Blb[sb],   &Bl[gb]);
            cpa16(&Blb[sb+4], &Bl[gb+4]);
        }
    };
    auto domma = [&](uint32_t buf, int c){
        uint32_t aoff = buf*2048u;
        uint32_t bloff = buf*(uint32_t)CW;
        uint32_t bhoff = (uint32_t)(c*CW);
        #pragma unroll
        for (int h = 0; h < 2; h++){
            uint4 aH[2], aL[2];
            #pragma unroll
            for (int i = 0; i < 2; i++){
                uint32_t sb = aoff + (uint32_t)((h*8 + 2*mw + i)*128 + lane*4);
                aH[i] = *(const uint4*)&Ah_s[sb];
                aL[i] = *(const uint4*)&Al_s[sb];
            }
            #pragma unroll
            for (int ch = 0; ch < COUT/128; ch++){
                #pragma unroll
                for (int half = 0; half < 2; half++){
                    int jj0 = nw*4 + half*2;
                    uint32_t idx = (uint32_t)((h*(COUT/16) + ch*8 + jj0)*128 + lane*4);
                    uint4 bH0 = *(const uint4*)&Bh_r[bhoff + idx];
                    uint4 bH1 = *(const uint4*)&Bh_r[bhoff + idx + 128];
                    uint4 bL0 = *(const uint4*)&Blb[bloff + idx];
                    uint4 bL1 = *(const uint4*)&Blb[bloff + idx + 128];
                    #pragma unroll
                    for (int i = 0; i < 2; i++){
                        mma3(acc[ch][i][half*4+0], aH[i], aL[i], bH0.x, bH0.y, bL0.x, bL0.y);
                        mma3(acc[ch][i][half*4+1], aH[i], aL[i], bH0.z, bH0.w, bL0.z, bL0.w);
                        mma3(acc[ch][i][half*4+2], aH[i], aL[i], bH1.x, bH1.y, bL1.x, bL1.y);
                        mma3(acc[ch][i][half*4+3], aH[i], aL[i], bH1.z, bH1.w, bL1.z, bL1.w);
                    }
                }
            }
        }
    };

    // prologue: resident Bh load + chunk 0
    for (int idx = tid*4; idx < NC*CW; idx += 1024)
        cpa16(&Bh_r[idx], &Bh[idx]);
    ldgA(L0, 0);
    cpBl(0, 0);
    CP_COMMIT();
    stsA(L0, 0, 0);
    if (NC > 1) ldgA(L1, 1);
    CP_WAIT0();
    __syncthreads();

    #pragma unroll
    for (int cb = 0; cb < NC; cb += 2){
        { // even chunk -> buffer 0
            int c = cb;
            if (c+1 < NC){ cpBl(c+1, 1); CP_COMMIT(); }
            if (c+2 < NC) ldgA(L0, c+2);
            domma(0, c);
            if (c+1 < NC){ stsA(L1, c+1, 1); CP_WAIT0(); }
            __syncthreads();
        }
        if (cb+1 < NC){ // odd chunk -> buffer 1
            int c = cb+1;
            if (c+1 < NC){ cpBl(c+1, 0); CP_COMMIT(); }
            if (c+2 < NC) ldgA(L1, c+2);
            domma(1, c);
            if (c+1 < NC){ stsA(L0, c+1, 0); CP_WAIT0(); }
            __syncthreads();
        }
    }

    #pragma unroll
    for (int ch = 0; ch < COUT/128; ch++){
        #pragma unroll
        for (int i = 0; i < 2; i++){
            #pragma unroll
            for (int j = 0; j < 8; j++){
                int col = ch*128 + nw*64 + j*8 + 2*q;
                int r   = row0 + mw*32 + i*16 + gr;
                float2 lo = make_float2(acc[ch][i][j][0], acc[ch][i][j][1]);
                float2 hi = make_float2(acc[ch][i][j][2], acc[ch][i][j][3]);
                if (ADD_BIAS){
                    float bx = bias[col], by = bias[col+1];
                    lo.x += bx; lo.y += by; hi.x += bx; hi.y += by;
                }
                *(float2*)&Y[(size_t)r*COUT + col]     = lo;
                *(float2*)&Y[(size_t)(r+8)*COUT + col] = hi;
            }
        }
    }
    if (STATS){
        #pragma unroll
        for (int ch = 0; ch < COUT/128; ch++){
            #pragma unroll
            for (int j = 0; j < 8; j++){
                float se = acc[ch][0][j][0] + acc[ch][0][j][2] + acc[ch][1][j][0] + acc[ch][1][j][2];
                float so = acc[ch][0][j][1] + acc[ch][0][j][3] + acc[ch][1][j][1] + acc[ch][1][j][3];
                float qe = acc[ch][0][j][0]*acc[ch][0][j][0] + acc[ch][0][j][2]*acc[ch][0][j][2]
                         + acc[ch][1][j][0]*acc[ch][1][j][0] + acc[ch][1][j][2]*acc[ch][1][j][2];
                float qo = acc[ch][0][j][1]*acc[ch][0][j][1] + acc[ch][0][j][3]*acc[ch][0][j][3]
                         + acc[ch][1][j][1]*acc[ch][1][j][1] + acc[ch][1][j][3]*acc[ch][1][j][3];
                #pragma unroll
                for (int m = 4; m <= 16; m <<= 1){
                    se += __shfl_xor_sync(0xFFFFFFFFu, se, m);
                    so += __shfl_xor_sync(0xFFFFFFFFu, so, m);
                    qe += __shfl_xor_sync(0xFFFFFFFFu, qe, m);
                    qo += __shfl_xor_sync(0xFFFFFFFFu, qo, m);
                }
                if (lane < 4){
                    int col = ch*128 + nw*64 + j*8 + 2*q;
                    atomicAdd(&sstat[col],        se);
                    atomicAdd(&sstat[col+1],      so);
                    atomicAdd(&sstat[COUT+col],   qe);
                    atomicAdd(&sstat[COUT+col+1], qo);
                }
            }
        }
        __syncthreads();
        for (int i = tid; i < 2*COUT; i += 256){
            int c2 = (i < COUT) ? i : (i - COUT);
            atomicAdd(&statp[(i < COUT ? 0 : 256) + c2], sstat[i]);
        }
    }
}

// ---- voxel compress ----
__global__ __launch_bounds__(256) void comp_k(const float* __restrict__ bc){
    extern __shared__ char smem[];
    uint32_t* Bh_s = (uint32_t*)smem;
    uint32_t* Bl_s = Bh_s + 8192;
    uint32_t* Ah_s = Bl_s + 8192;
    uint32_t* Al_s = Ah_s + 4096;
    int* scnt = (int*)(Al_s + 4096);
    int* soff = scnt + 128;

    int tid = threadIdx.x, wid = tid >> 5, lane = tid & 31;
    int gr = lane >> 2, q = lane & 3;
    int row0 = blockIdx.x*128;
    int mw = wid & 3, nw = wid >> 2, fw = wid;

    for (int idx = tid*4; idx < 8192; idx += 1024){
        cpa16(&Bh_s[idx], &g_wch[idx]);
        cpa16(&Bl_s[idx], &g_wcl[idx]);
    }
    CP_COMMIT();
    if (tid < 128){ scnt[tid] = g_cnt[row0+tid]; soff[tid] = g_off[row0+tid]; }

    float acc[2][4][4];
    #pragma unroll
    for (int i = 0; i < 2; i++)
        #pragma unroll
        for (int j = 0; j < 4; j++)
            #pragma unroll
            for (int cc = 0; cc < 4; cc++) acc[i][j][cc] = 0.0f;

    CP_WAIT0();
    __syncthreads();

    int lv0 = 16*fw + gr, lv1 = lv0 + 8;
    int cnt0 = scnt[lv0], off0 = soff[lv0];
    int cnt1 = scnt[lv1], off1 = soff[lv1];

    float2 M0[4], M1[4];
    auto gather = [&](int c){
        int kbase = c*32 + 2*q;
        if (cnt0 <= 0){
            #pragma unroll
            for (int t = 0; t < 4; t++) M0[t] = make_float2(0,0);
        } else {
            const float* p = &g_y4[(size_t)off0*256 + kbase];
            M0[0]=*(const float2*)p; M0[1]=*(const float2*)(p+8);
            M0[2]=*(const float2*)(p+16); M0[3]=*(const float2*)(p+24);
            for (int jj = 1; jj < cnt0; jj++){
                const float* pj = p + (size_t)jj*256;
                float2 w;
                w=*(const float2*)pj;      M0[0].x=fmaxf(M0[0].x,w.x); M0[0].y=fmaxf(M0[0].y,w.y);
                w=*(const float2*)(pj+8);  M0[1].x=fmaxf(M0[1].x,w.x); M0[1].y=fmaxf(M0[1].y,w.y);
                w=*(const float2*)(pj+16); M0[2].x=fmaxf(M0[2].x,w.x); M0[2].y=fmaxf(M0[2].y,w.y);
                w=*(const float2*)(pj+24); M0[3].x=fmaxf(M0[3].x,w.x); M0[3].y=fmaxf(M0[3].y,w.y);
            }
        }
        if (cnt1 <= 0){
            #pragma unroll
            for (int t = 0; t < 4; t++) M1[t] = make_float2(0,0);
        } else {
            const float* p = &g_y4[(size_t)off1*256 + kbase];
            M1[0]=*(const float2*)p; M1[1]=*(const float2*)(p+8);
            M1[2]=*(const float2*)(p+16); M1[3]=*(const float2*)(p+24);
            for (int jj = 1; jj < cnt1; jj++){
                const float* pj = p + (size_t)jj*256;
                float2 w;
                w=*(const float2*)pj;      M1[0].x=fmaxf(M1[0].x,w.x); M1[0].y=fmaxf(M1[0].y,w.y);
                w=*(const float2*)(pj+8);  M1[1].x=fmaxf(M1[1].x,w.x); M1[1].y=fmaxf(M1[1].y,w.y);
                w=*(const float2*)(pj+16); M1[2].x=fmaxf(M1[2].x,w.x); M1[2].y=fmaxf(M1[2].y,w.y);
                w=*(const float2*)(pj+24); M1[3].x=fmaxf(M1[3].x,w.x); M1[3].y=fmaxf(M1[3].y,w.y);
            }
        }
    };
    auto storeA = [&](uint32_t buf){
        #pragma unroll
        for (int h = 0; h < 2; h++){
            uint32_t r0h,r0l,r1h,r1l,r2h,r2l,r3h,r3l;
            split2(M0[h*2+0].x, M0[h*2+0].y, r0h, r0l);
            split2(M1[h*2+0].x, M1[h*2+0].y, r1h, r1l);
            split2(M0[h*2+1].x, M0[h*2+1].y, r2h, r2l);
            split2(M1[h*2+1].x, M1[h*2+1].y, r3h, r3l);
            uint32_t sb = buf*2048u + (uint32_t)((h*8 + fw)*128 + lane*4);
            *(uint4*)&Ah_s[sb] = make_uint4(r0h,r1h,r2h,r3h);
            *(uint4*)&Al_s[sb] = make_uint4(r0l,r1l,r2l,r3l);
        }
    };

    gather(0);
    storeA(0);
    __syncthreads();

    for (int c = 0; c < 8; c++){
        int buf = c & 1, nbuf = buf ^ 1;
        if (c+1 < 8) gather(c+1);
        uint32_t aoff = (uint32_t)buf*2048;
        #pragma unroll
        for (int h = 0; h < 2; h++){
            uint4 aH[2], aL[2];
            #pragma unroll
            for (int i = 0; i < 2; i++){
                uint32_t sb = aoff + (uint32_t)((h*8 + 2*mw + i)*128 + lane*4);
                aH[i] = *(const uint4*)&Ah_s[sb];
                aL[i] = *(const uint4*)&Al_s[sb];
            }
            int jj0 = nw*2;
            uint32_t base = (uint32_t)(c*1024 + (h*4 + jj0)*128 + lane*4);
            uint4 bH0 = *(const uint4*)&Bh_s[base];
            uint4 bH1 = *(const uint4*)&Bh_s[base + 128];
            uint4 bL0 = *(const uint4*)&Bl_s[base];
            uint4 bL1 = *(const uint4*)&Bl_s[base + 128];
            #pragma unroll
            for (int i = 0; i < 2; i++){
                mma3(acc[i][0], aH[i], aL[i], bH0.x, bH0.y, bL0.x, bL0.y);
                mma3(acc[i][1], aH[i], aL[i], bH0.z, bH0.w, bL0.z, bL0.w);
                mma3(acc[i][2], aH[i], aL[i], bH1.x, bH1.y, bL1.x, bL1.y);
                mma3(acc[i][3], aH[i], aL[i], bH1.z, bH1.w, bL1.z, bL1.w);
            }
        }
        if (c+1 < 8) storeA((uint32_t)nbuf);
        __syncthreads();
    }

    #pragma unroll
    for (int i = 0; i < 2; i++){
        #pragma unroll
        for (int j = 0; j < 4; j++){
            int cl = nw*32 + j*8 + 2*q;
            int r  = mw*32 + i*16 + gr;
            float m0 = (scnt[r]   > 0) ? 1.0f : 0.0f;
            float m1 = (scnt[r+8] > 0) ? 1.0f : 0.0f;
            float bx = bc[cl], by = bc[cl+1];
            float2 lo, hi;
            lo.x = fmaxf(acc[i][j][0] + bx, 0.0f)*m0;
            lo.y = fmaxf(acc[i][j][1] + by, 0.0f)*m0;
            hi.x = fmaxf(acc[i][j][2] + bx, 0.0f)*m1;
            hi.y = fmaxf(acc[i][j][3] + by, 0.0f)*m1;
            *(float2*)&g_comp[(size_t)(row0 + r)*64 + cl]     = lo;
            *(float2*)&g_comp[(size_t)(row0 + r + 8)*64 + cl] = hi;
        }
    }
}

__global__ __launch_bounds__(256) void residual_k(float* __restrict__ out){
    int idx = blockIdx.x*blockDim.x + threadIdx.x;
    const int TOT = BB*192*HH*WW;
    if (idx >= TOT) return;
    int w  = idx % WW;
    int h  = (idx / WW) % HH;
    int ch = (idx / (WW*HH)) % 192;
    int b  = idx / (WW*HH*192);
    int f = ch >> 6, j = ch & 63;
    int vl = ((b*FF + (FF-1))*HH + h)*WW + w;
    int vf = ((b*FF + f)*HH + h)*WW + w;
    out[idx] = g_comp[(size_t)vl*64 + j] - g_comp[(size_t)vf*64 + j];
}

extern "C" void kernel_launch(void* const* d_in, const int* in_sizes, int n_in,
                              void* d_out, int out_size){
    const float* pts   = (const float*)d_in[0];
    const int*   coors = (const int*)  d_in[1];
    const float* pre_g = (const float*)d_in[2];
    const float* pre_b = (const float*)d_in[3];
    const float* W1    = (const float*)d_in[4];
    const float* g1    = (const float*)d_in[5];
    const float* b1    = (const float*)d_in[6];
    const float* W2    = (const float*)d_in[7];
    const float* g2    = (const float*)d_in[8];
    const float* b2    = (const float*)d_in[9];
    const float* W3    = (const float*)d_in[10];
    const float* g3    = (const float*)d_in[11];
    const float* b3    = (const float*)d_in[12];
    const float* W4    = (const float*)d_in[13];
    const float* b4    = (const float*)d_in[14];
    const float* Wc    = (const float*)d_in[15];
    const float* bc    = (const float*)d_in[16];
    float* out = (float*)d_out;

    void *py1, *py2, *py3, *py4, *pstat;
    void *p2h,*p2l,*p3h,*p3l,*p4h,*p4l;
    cudaGetSymbolAddress(&py1, g_y1);
    cudaGetSymbolAddress(&py2, g_y2);
    cudaGetSymbolAddress(&py3, g_y3);
    cudaGetSymbolAddress(&py4, g_y4);
    cudaGetSymbolAddress(&pstat, g_stat);
    cudaGetSymbolAddress(&p2h, g_w2h); cudaGetSymbolAddress(&p2l, g_w2l);
    cudaGetSymbolAddress(&p3h, g_w3h); cudaGetSymbolAddress(&p3l, g_w3l);
    cudaGetSymbolAddress(&p4h, g_w4h); cudaGetSymbolAddress(&p4l, g_w4l);
    float* statb = (float*)pstat;

    // smem bytes: A(32768) + Bl(2*CW*4) + Bh_r(NC*CW*4) + stats(2*COUT*4)
    const int SM_L2 = 32768 + 2*128*16*4 + 2*128*16*4 + 2*128*4;       // 66 KB
    const int SM_L3 = 32768 + 2*256*16*4 + 4*256*16*4 + 2*256*4;       // 132 KB
    const int SM_L4 = 32768 + 2*256*16*4 + 8*256*16*4 + 2*256*4;       // 197.5 KB
    const int SM_COMP = 65536 + 32768 + 2*128*4;
    static bool attr_set = false;
    if (!attr_set){
        cudaFuncSetAttribute(mm_k<64,128,false,true>,  cudaFuncAttributeMaxDynamicSharedMemorySize, SM_L2);
        cudaFuncSetAttribute(mm_k<128,256,false,true>, cudaFuncAttributeMaxDynamicSharedMemorySize, SM_L3);
        cudaFuncSetAttribute(mm_k<256,256,true,false>, cudaFuncAttributeMaxDynamicSharedMemorySize, SM_L4);
        cudaFuncSetAttribute(comp_k, cudaFuncAttributeMaxDynamicSharedMemorySize, SM_COMP);
        attr_set = true;
    }

    init_k<<<1024, 256>>>();
    tr_all_k<<<240, 256>>>(W2, W3, W4, Wc);
    scatter_k<<<N_PTS/256, 256>>>(pts, coors);
    scan1_k<<<SS/1024, 1024>>>();
    scan2_k<<<1, 256>>>();
    scan3_k<<<SS/1024, 1024>>>();
    csrfeats_k<<<N_PTS/256, 256>>>(pts);
    bnparam_k<<<1, 256>>>(pre_g, pre_b, 8, 0);

    gemm1_k<<<N_PTS/128, 128>>>(W1);
    stats_k<<<2048, 256>>>((const float*)py1);
    bnparam_k<<<1, 256>>>(g1, b1, 64, 1);

    mm_k<64,128,false,true><<<N_PTS/128, 256, SM_L2>>>(
        (const float*)py1, (const uint32_t*)p2h, (const uint32_t*)p2l,
        (float*)py2, nullptr, 1, statb + 2*512);
    bnparam_k<<<1, 256>>>(g2, b2, 128, 2);

    mm_k<128,256,false,true><<<N_PTS/128, 256, SM_L3>>>(
        (const float*)py2, (const uint32_t*)p3h, (const uint32_t*)p3l,
        (float*)py3, nullptr, 2, statb + 3*512);
    bnparam_k<<<1, 256>>>(g3, b3, 256, 3);

    mm_k<256,256,true,false><<<N_PTS/128, 256, SM_L4>>>(
        (const float*)py3, (const uint32_t*)p4h, (const uint32_t*)p4l,
        (float*)py4, b4, 3, nullptr);

    comp_k<<<SS/128, 256, SM_COMP>>>(bc);

    const int TOT = BB*192*HH*WW;
    residual_k<<<(TOT + 255)/256, 256>>>(out);

    (void)in_sizes; (void)n_in; (void)out_size;
}

// round 14
// speedup vs baseline: 1.3017x; 1.1336x over previous
#include <cuda_runtime.h>
#include <cuda_bf16.h>
#include <cstdint>
#include <cstddef>

#define N_PTS 524288
#define BB 2
#define FF 4
#define HH 64
#define WW 512
#define SS (BB*FF*HH*WW)
#define EPSBN 1e-5f

__device__ int   g_cnt[SS];
__device__ int   g_off[SS];
__device__ int   g_cursor[SS];
__device__ int   g_bsum[256];
__device__ int   g_boff[256];
__device__ float g_vsum[SS*3];
__device__ int   g_lin[N_PTS];
__device__ float g_feats[(size_t)N_PTS*8];
__device__ float g_y1[(size_t)N_PTS*64];
__device__ float g_y2[(size_t)N_PTS*128];
__device__ float g_y3[(size_t)N_PTS*256];
__device__ float g_y4[(size_t)N_PTS*256];
__device__ float g_comp[(size_t)SS*64];
__device__ float g_stat[4*512];
__device__ float g_scale[4*256];
__device__ float g_shift[4*256];
__device__ uint32_t g_w2h[4096],  g_w2l[4096];
__device__ uint32_t g_w3h[16384], g_w3l[16384];
__device__ uint32_t g_w4h[32768], g_w4l[32768];
__device__ uint32_t g_wch[8192],  g_wcl[8192];

__device__ __forceinline__ void split2(float x0, float x1, uint32_t& hi, uint32_t& lo){
    uint32_t h;
    asm("cvt.rn.bf16x2.f32 %0, %1, %2;" : "=r"(h) : "f"(x1), "f"(x0));
    float f0 = __uint_as_float(h << 16);
    float f1 = __uint_as_float(h & 0xFFFF0000u);
    float r0 = x0 - f0, r1 = x1 - f1;
    uint32_t l;
    asm("cvt.rn.bf16x2.f32 %0, %1, %2;" : "=r"(l) : "f"(r1), "f"(r0));
    hi = h; lo = l;
}
__device__ __forceinline__ void mma16(float* c, uint32_t a0, uint32_t a1, uint32_t a2, uint32_t a3,
                                      uint32_t b0, uint32_t b1){
    asm volatile(
        "mma.sync.aligned.m16n8k16.row.col.f32.bf16.bf16.f32 "
        "{%0,%1,%2,%3}, {%4,%5,%6,%7}, {%8,%9}, {%0,%1,%2,%3};"
        : "+f"(c[0]), "+f"(c[1]), "+f"(c[2]), "+f"(c[3])
        : "r"(a0), "r"(a1), "r"(a2), "r"(a3), "r"(b0), "r"(b1));
}
__device__ __forceinline__ void mma3(float* c, const uint4& aH, const uint4& aL,
                                     uint32_t bh0, uint32_t bh1, uint32_t bl0, uint32_t bl1){
    mma16(c, aH.x, aH.y, aH.z, aH.w, bh0, bh1);
    mma16(c, aH.x, aH.y, aH.z, aH.w, bl0, bl1);
    mma16(c, aL.x, aL.y, aL.z, aL.w, bh0, bh1);
}
__device__ __forceinline__ void cpa16(void* s, const void* g){
    uint32_t sa = (uint32_t)__cvta_generic_to_shared(s);
    asm volatile("cp.async.ca.shared.global [%0], [%1], 16;" :: "r"(sa), "l"(g) : "memory");
}
#define CP_COMMIT() asm volatile("cp.async.commit_group;" ::: "memory")
#define CP_WAIT0()  asm volatile("cp.async.wait_group 0;" ::: "memory")

__global__ void init_k(){
    long stride = (long)gridDim.x * blockDim.x;
    for (long i = (long)blockIdx.x*blockDim.x + threadIdx.x; i < (long)SS*3; i += stride){
        g_vsum[i] = 0.0f;
        if (i < SS) g_cnt[i] = 0;
        if (i < 4*512) g_stat[i] = 0.0f;
    }
}

__global__ __launch_bounds__(256) void scatter_k(const float* __restrict__ pts,
                                                 const int* __restrict__ coors){
    int i = blockIdx.x*blockDim.x + threadIdx.x;
    if (i >= N_PTS) return;
    int c0 = coors[4*i+0], c1 = coors[4*i+1], c2 = coors[4*i+2], c3 = coors[4*i+3];
    int l = ((c0*FF + c1)*HH + c2)*WW + c3;
    g_lin[i] = l;
    float4 p = *(const float4*)&pts[4*i];
    atomicAdd(&g_cnt[l], 1);
    atomicAdd(&g_vsum[3*l+0], p.x);
    atomicAdd(&g_vsum[3*l+1], p.y);
    atomicAdd(&g_vsum[3*l+2], p.z);
}

__global__ __launch_bounds__(1024) void scan1_k(){
    __shared__ int s[1024];
    int t = threadIdx.x, g = blockIdx.x*1024 + t;
    int v = g_cnt[g]; s[t] = v; __syncthreads();
    #pragma unroll
    for (int d = 1; d < 1024; d <<= 1){
        int x = (t >= d) ? s[t-d] : 0; __syncthreads();
        s[t] += x; __syncthreads();
    }
    g_off[g] = s[t] - v;
    if (t == 1023) g_bsum[blockIdx.x] = s[t];
}
__global__ void scan2_k(){
    __shared__ int s[256];
    int t = threadIdx.x;
    int v = g_bsum[t]; s[t] = v; __syncthreads();
    #pragma unroll
    for (int d = 1; d < 256; d <<= 1){
        int x = (t >= d) ? s[t-d] : 0; __syncthreads();
        s[t] += x; __syncthreads();
    }
    g_boff[t] = s[t] - v;
}
__global__ __launch_bounds__(1024) void scan3_k(){
    int g = blockIdx.x*1024 + threadIdx.x;
    int o = g_off[g] + g_boff[blockIdx.x];
    g_off[g] = o; g_cursor[g] = o;
}

__global__ __launch_bounds__(256) void csrfeats_k(const float* __restrict__ pts){
    __shared__ float st[16];
    int tid = threadIdx.x;
    if (tid < 16) st[tid] = 0.0f;
    __syncthreads();
    int i = blockIdx.x*256 + tid;
    int l = g_lin[i];
    int slot = atomicAdd(&g_cursor[l], 1);
    float4 p = *(const float4*)&pts[4*i];
    float inv = 1.0f / fmaxf((float)g_cnt[l], 1.0f);
    float mx = g_vsum[3*l+0]*inv, my = g_vsum[3*l+1]*inv, mz = g_vsum[3*l+2]*inv;
    float f[8];
    f[0]=p.x; f[1]=p.y; f[2]=p.z; f[3]=p.w;
    f[4]=sqrtf(p.x*p.x + p.y*p.y + p.z*p.z);
    f[5]=p.x-mx; f[6]=p.y-my; f[7]=p.z-mz;
    *(float4*)&g_feats[(size_t)slot*8]   = make_float4(f[0],f[1],f[2],f[3]);
    *(float4*)&g_feats[(size_t)slot*8+4] = make_float4(f[4],f[5],f[6],f[7]);
    #pragma unroll
    for (int ch = 0; ch < 8; ch++){
        float s = f[ch], q = f[ch]*f[ch];
        #pragma unroll
        for (int o = 16; o; o >>= 1){
            s += __shfl_xor_sync(0xFFFFFFFFu, s, o);
            q += __shfl_xor_sync(0xFFFFFFFFu, q, o);
        }
        if ((tid & 31) == 0){ atomicAdd(&st[ch], s); atomicAdd(&st[8+ch], q); }
    }
    __syncthreads();
    if (tid < 8)       atomicAdd(&g_stat[tid], st[tid]);
    else if (tid < 16) atomicAdd(&g_stat[256 + tid - 8], st[tid]);
}

__global__ void bnparam_k(const float* __restrict__ gam, const float* __restrict__ bet,
                          int C, int layer){
    int c = threadIdx.x;
    if (c < C){
        float n = (float)N_PTS;
        float m = g_stat[layer*512 + c] / n;
        float v = g_stat[layer*512 + 256 + c] / n - m*m;
        float sc = gam[c] / sqrtf(v + EPSBN);
        g_scale[layer*256+c] = sc;
        g_shift[layer*256+c] = bet[c] - m*sc;
    }
}

// layer 1 with FUSED y1 column stats (smem tile + 2-thread/col reduce)
__global__ __launch_bounds__(128) void gemm1_k(const float* __restrict__ W1){
    __shared__ float Ws[8][64];
    __shared__ float sc[8], sh[8];
    __shared__ float tile[128][65];
    int tid = threadIdx.x;
    for (int i = tid; i < 512; i += 128) Ws[i>>6][i&63] = W1[i];
    if (tid < 8){ sc[tid] = g_scale[tid]; sh[tid] = g_shift[tid]; }
    __syncthreads();
    int row = blockIdx.x*128 + tid;
    float4 fa = *(const float4*)&g_feats[(size_t)row*8];
    float4 fb = *(const float4*)&g_feats[(size_t)row*8+4];
    float f[8] = {fa.x,fa.y,fa.z,fa.w,fb.x,fb.y,fb.z,fb.w};
    #pragma unroll
    for (int k = 0; k < 8; k++) f[k] = f[k]*sc[k] + sh[k];
    #pragma unroll
    for (int c4 = 0; c4 < 16; c4++){
        float4 acc = make_float4(0,0,0,0);
        #pragma unroll
        for (int k = 0; k < 8; k++){
            float4 w = *(const float4*)&Ws[k][c4*4];
            acc.x += f[k]*w.x; acc.y += f[k]*w.y;
            acc.z += f[k]*w.z; acc.w += f[k]*w.w;
        }
        *(float4*)&g_y1[(size_t)row*64 + c4*4] = acc;
        tile[tid][c4*4+0] = acc.x; tile[tid][c4*4+1] = acc.y;
        tile[tid][c4*4+2] = acc.z; tile[tid][c4*4+3] = acc.w;
    }
    __syncthreads();
    int c = tid & 63, half = tid >> 6;
    float s = 0.0f, q = 0.0f;
    #pragma unroll 8
    for (int r = half*64; r < half*64 + 64; r++){
        float v = tile[r][c];
        s += v; q += v*v;
    }
    atomicAdd(&g_stat[512 + c], s);
    atomicAdd(&g_stat[512 + 256 + c], q);
}

__device__ __forceinline__ void tr_body(const float* __restrict__ W,
                                        uint32_t* __restrict__ Wh,
                                        uint32_t* __restrict__ Wl,
                                        int Kd, int Cd, int blk){
    int i = blk*256 + threadIdx.x;
    if (i >= Cd*Kd/2) return;
    int n = i / (Kd/2);
    int k = 2*(i % (Kd/2));
    int c = k >> 5, h = (k >> 4) & 1;
    int kp16 = (k >> 1) & 7;
    int q = kp16 & 3, rb = kp16 >> 2;
    int j = n >> 3, gr = n & 7;
    int jj = j >> 1, jpar = j & 1;
    int addr = c*(Cd*16) + (h*(Cd/16) + jj)*128 + (gr*4+q)*4 + jpar*2 + rb;
    uint32_t hi, lo;
    split2(W[(size_t)k*Cd + n], W[(size_t)(k+1)*Cd + n], hi, lo);
    Wh[addr] = hi; Wl[addr] = lo;
}
__global__ __launch_bounds__(256) void tr_all_k(const float* __restrict__ W2,
                                                const float* __restrict__ W3,
                                                const float* __restrict__ W4,
                                                const float* __restrict__ Wc){
    int b = blockIdx.x;
    if (b < 16)       tr_body(W2, g_w2h, g_w2l, 64, 128, b);
    else if (b < 80)  tr_body(W3, g_w3h, g_w3l, 128, 256, b-16);
    else if (b < 208) tr_body(W4, g_w4h, g_w4l, 256, 256, b-80);
    else              tr_body(Wc, g_wch, g_wcl, 256, 64, b-208);
}

// ---- bf16x3 GEMM: 2m x 4n warp tiling (64m x 64n warp tile), resident Bh,
//      streamed Bl, depth-2 A prefetch, static parity ----
template<int K, int COUT, bool ADD_BIAS, bool STATS>
__global__ __launch_bounds__(256) void mm_k(const float* __restrict__ A,
                                            const uint32_t* __restrict__ Bh,
                                            const uint32_t* __restrict__ Bl,
                                            float* __restrict__ Y,
                                            const float* __restrict__ bias,
                                            int layer, float* __restrict__ statp){
    constexpr int NC = K/32;           // even: 2, 4, 8
    constexpr int CW = COUT*16;        // words per B chunk
    constexpr int J16W = COUT/64;      // j16 blocks per n-warp (4 for 256, 2 for 128)
    constexpr int NJ = 2*J16W;         // j8 blocks per n-warp
    extern __shared__ char smem[];
    uint32_t* Ah_s = (uint32_t*)smem;            // [2][2048]
    uint32_t* Al_s = Ah_s + 4096;                // [2][2048]
    uint32_t* Blb  = Al_s + 4096;                // [2][CW]
    uint32_t* Bh_r = Blb + 2*CW;                 // [NC*CW]
    float*    sstat = (float*)(Bh_r + NC*CW);

    int tid = threadIdx.x, wid = tid >> 5, lane = tid & 31;
    int gr = lane >> 2, q = lane & 3;
    int row0 = blockIdx.x*128;
    int mw = wid & 1, nw = wid >> 1, fw = wid;
    int ar0 = row0 + 16*fw + gr;
    int b16 = tid >> 4, h_b = b16 >> 3, jj_b = b16 & 7, l16 = tid & 15;

    if (STATS){
        for (int i = tid; i < 2*COUT; i += 256) sstat[i] = 0.0f;
    }

    float acc[4][NJ][4];
    #pragma unroll
    for (int i = 0; i < 4; i++)
        #pragma unroll
        for (int j = 0; j < NJ; j++)
            #pragma unroll
            for (int cc = 0; cc < 4; cc++) acc[i][j][cc] = 0.0f;

    const float* scp = &g_scale[layer*256];
    const float* shp = &g_shift[layer*256];

    float2 L0[2][4], L1[2][4];

    auto ldgA = [&](float2 (&Ls)[2][4], int c){
        #pragma unroll
        for (int h = 0; h < 2; h++){
            const float* p0 = A + (size_t)ar0*K + c*32 + 16*h + 2*q;
            Ls[h][0] = *(const float2*)p0;
            Ls[h][1] = *(const float2*)(p0 + 8);
            const float* p1 = p0 + (size_t)8*K;
            Ls[h][2] = *(const float2*)p1;
            Ls[h][3] = *(const float2*)(p1 + 8);
        }
    };
    auto stsA = [&](float2 (&Ls)[2][4], int c, uint32_t buf){
        #pragma unroll
        for (int h = 0; h < 2; h++){
            int kb = c*32 + 16*h + 2*q;
            float2 sA = *(const float2*)&scp[kb],   hA = *(const float2*)&shp[kb];
            float2 sB = *(const float2*)&scp[kb+8], hB = *(const float2*)&shp[kb+8];
            uint32_t r0h,r0l,r1h,r1l,r2h,r2l,r3h,r3l;
            split2(fmaxf(Ls[h][0].x*sA.x + hA.x, 0.0f), fmaxf(Ls[h][0].y*sA.y + hA.y, 0.0f), r0h, r0l);
            split2(fmaxf(Ls[h][2].x*sA.x + hA.x, 0.0f), fmaxf(Ls[h][2].y*sA.y + hA.y, 0.0f), r1h, r1l);
            split2(fmaxf(Ls[h][1].x*sB.x + hB.x, 0.0f), fmaxf(Ls[h][1].y*sB.y + hB.y, 0.0f), r2h, r2l);
            split2(fmaxf(Ls[h][3].x*sB.x + hB.x, 0.0f), fmaxf(Ls[h][3].y*sB.y + hB.y, 0.0f), r3h, r3l);
            uint32_t sb = buf*2048u + (uint32_t)((h*8 + fw)*128 + lane*4);
            *(uint4*)&Ah_s[sb] = make_uint4(r0h,r1h,r2h,r3h);
            *(uint4*)&Al_s[sb] = make_uint4(r0l,r1l,r2l,r3l);
        }
    };
    auto cpBl = [&](int c, uint32_t buf){
        #pragma unroll
        for (int rep = 0; rep < COUT/128; rep++){
            uint32_t off = (uint32_t)((h_b*(COUT/16) + rep*8 + jj_b)*128 + l16*8);
            size_t gb = (size_t)c*CW + off;
            uint32_t sb = buf*(uint32_t)CW + off;
            cpa16(&Blb[sb],   &Bl[gb]);
            cpa16(&Blb[sb+4], &Bl[gb+4]);
        }
    };
    auto domma = [&](uint32_t buf, int c){
        uint32_t aoff = buf*2048u;
        uint32_t bloff = buf*(uint32_t)CW;
        uint32_t bhoff = (uint32_t)(c*CW);
        #pragma unroll
        for (int h = 0; h < 2; h++){
            uint4 aH[4], aL[4];
            #pragma unroll
            for (int i = 0; i < 4; i++){
                uint32_t sb = aoff + (uint32_t)((h*8 + mw*4 + i)*128 + lane*4);
                aH[i] = *(const uint4*)&Ah_s[sb];
                aL[i] = *(const uint4*)&Al_s[sb];
            }
            #pragma unroll
            for (int jb = 0; jb < J16W; jb++){
                uint32_t idx = (uint32_t)((h*(COUT/16) + nw*J16W + jb)*128 + lane*4);
                uint4 bH = *(const uint4*)&Bh_r[bhoff + idx];
                uint4 bL = *(const uint4*)&Blb[bloff + idx];
                #pragma unroll
                for (int i = 0; i < 4; i++){
                    mma3(acc[i][2*jb+0], aH[i], aL[i], bH.x, bH.y, bL.x, bL.y);
                    mma3(acc[i][2*jb+1], aH[i], aL[i], bH.z, bH.w, bL.z, bL.w);
                }
            }
        }
    };

    // prologue
    for (int idx = tid*4; idx < NC*CW; idx += 1024)
        cpa16(&Bh_r[idx], &Bh[idx]);
    ldgA(L0, 0);
    cpBl(0, 0);
    CP_COMMIT();
    stsA(L0, 0, 0);
    if (NC > 1) ldgA(L1, 1);
    CP_WAIT0();
    __syncthreads();

    #pragma unroll
    for (int cb = 0; cb < NC; cb += 2){
        { int c = cb;
            if (c+1 < NC){ cpBl(c+1, 1); CP_COMMIT(); }
            if (c+2 < NC) ldgA(L0, c+2);
            domma(0, c);
            if (c+1 < NC){ stsA(L1, c+1, 1); CP_WAIT0(); }
            __syncthreads();
        }
        if (cb+1 < NC){ int c = cb+1;
            if (c+1 < NC){ cpBl(c+1, 0); CP_COMMIT(); }
            if (c+2 < NC) ldgA(L1, c+2);
            domma(1, c);
            if (c+1 < NC){ stsA(L0, c+1, 0); CP_WAIT0(); }
            __syncthreads();
        }
    }

    #pragma unroll
    for (int i = 0; i < 4; i++){
        #pragma unroll
        for (int j = 0; j < NJ; j++){
            int col = nw*(COUT/4) + j*8 + 2*q;
            int r   = row0 + mw*64 + i*16 + gr;
            float2 lo = make_float2(acc[i][j][0], acc[i][j][1]);
            float2 hi = make_float2(acc[i][j][2], acc[i][j][3]);
            if (ADD_BIAS){
                float bx = bias[col], by = bias[col+1];
                lo.x += bx; lo.y += by; hi.x += bx; hi.y += by;
            }
            *(float2*)&Y[(size_t)r*COUT + col]     = lo;
            *(float2*)&Y[(size_t)(r+8)*COUT + col] = hi;
        }
    }
    if (STATS){
        #pragma unroll
        for (int j = 0; j < NJ; j++){
            float se = 0.0f, so = 0.0f, qe = 0.0f, qo = 0.0f;
            #pragma unroll
            for (int i = 0; i < 4; i++){
                se += acc[i][j][0] + acc[i][j][2];
                so += acc[i][j][1] + acc[i][j][3];
                qe += acc[i][j][0]*acc[i][j][0] + acc[i][j][2]*acc[i][j][2];
                qo += acc[i][j][1]*acc[i][j][1] + acc[i][j][3]*acc[i][j][3];
            }
            #pragma unroll
            for (int m = 4; m <= 16; m <<= 1){
                se += __shfl_xor_sync(0xFFFFFFFFu, se, m);
                so += __shfl_xor_sync(0xFFFFFFFFu, so, m);
                qe += __shfl_xor_sync(0xFFFFFFFFu, qe, m);
                qo += __shfl_xor_sync(0xFFFFFFFFu, qo, m);
            }
            if (lane < 4){
                int col = nw*(COUT/4) + j*8 + 2*q;
                atomicAdd(&sstat[col],        se);
                atomicAdd(&sstat[col+1],      so);
                atomicAdd(&sstat[COUT+col],   qe);
                atomicAdd(&sstat[COUT+col+1], qo);
            }
        }
        __syncthreads();
        for (int i = tid; i < 2*COUT; i += 256){
            int c2 = (i < COUT) ? i : (i - COUT);
            atomicAdd(&statp[(i < COUT ? 0 : 256) + c2], sstat[i]);
        }
    }
}

// ---- voxel compress ----
__global__ __launch_bounds__(256) void comp_k(const float* __restrict__ bc){
    extern __shared__ char smem[];
    uint32_t* Bh_s = (uint32_t*)smem;
    uint32_t* Bl_s = Bh_s + 8192;
    uint32_t* Ah_s = Bl_s + 8192;
    uint32_t* Al_s = Ah_s + 4096;
    int* scnt = (int*)(Al_s + 4096);
    int* soff = scnt + 128;

    int tid = threadIdx.x, wid = tid >> 5, lane = tid & 31;
    int gr = lane >> 2, q = lane & 3;
    int row0 = blockIdx.x*128;
    int mw = wid & 3, nw = wid >> 2, fw = wid;

    for (int idx = tid*4; idx < 8192; idx += 1024){
        cpa16(&Bh_s[idx], &g_wch[idx]);
        cpa16(&Bl_s[idx], &g_wcl[idx]);
    }
    CP_COMMIT();
    if (tid < 128){ scnt[tid] = g_cnt[row0+tid]; soff[tid] = g_off[row0+tid]; }

    float acc[2][4][4];
    #pragma unroll
    for (int i = 0; i < 2; i++)
        #pragma unroll
        for (int j = 0; j < 4; j++)
            #pragma unroll
            for (int cc = 0; cc < 4; cc++) acc[i][j][cc] = 0.0f;

    CP_WAIT0();
    __syncthreads();

    int lv0 = 16*fw + gr, lv1 = lv0 + 8;
    int cnt0 = scnt[lv0], off0 = soff[lv0];
    int cnt1 = scnt[lv1], off1 = soff[lv1];

    float2 M0[4], M1[4];
    auto gather = [&](int c){
        int kbase = c*32 + 2*q;
        if (cnt0 <= 0){
            #pragma unroll
            for (int t = 0; t < 4; t++) M0[t] = make_float2(0,0);
        } else {
            const float* p = &g_y4[(size_t)off0*256 + kbase];
            M0[0]=*(const float2*)p; M0[1]=*(const float2*)(p+8);
            M0[2]=*(const float2*)(p+16); M0[3]=*(const float2*)(p+24);
            for (int jj = 1; jj < cnt0; jj++){
                const float* pj = p + (size_t)jj*256;
                float2 w;
                w=*(const float2*)pj;      M0[0].x=fmaxf(M0[0].x,w.x); M0[0].y=fmaxf(M0[0].y,w.y);
                w=*(const float2*)(pj+8);  M0[1].x=fmaxf(M0[1].x,w.x); M0[1].y=fmaxf(M0[1].y,w.y);
                w=*(const float2*)(pj+16); M0[2].x=fmaxf(M0[2].x,w.x); M0[2].y=fmaxf(M0[2].y,w.y);
                w=*(const float2*)(pj+24); M0[3].x=fmaxf(M0[3].x,w.x); M0[3].y=fmaxf(M0[3].y,w.y);
            }
        }
        if (cnt1 <= 0){
            #pragma unroll
            for (int t = 0; t < 4; t++) M1[t] = make_float2(0,0);
        } else {
            const float* p = &g_y4[(size_t)off1*256 + kbase];
            M1[0]=*(const float2*)p; M1[1]=*(const float2*)(p+8);
            M1[2]=*(const float2*)(p+16); M1[3]=*(const float2*)(p+24);
            for (int jj = 1; jj < cnt1; jj++){
                const float* pj = p + (size_t)jj*256;
                float2 w;
                w=*(const float2*)pj;      M1[0].x=fmaxf(M1[0].x,w.x); M1[0].y=fmaxf(M1[0].y,w.y);
                w=*(const float2*)(pj+8);  M1[1].x=fmaxf(M1[1].x,w.x); M1[1].y=fmaxf(M1[1].y,w.y);
                w=*(const float2*)(pj+16); M1[2].x=fmaxf(M1[2].x,w.x); M1[2].y=fmaxf(M1[2].y,w.y);
                w=*(const float2*)(pj+24); M1[3].x=fmaxf(M1[3].x,w.x); M1[3].y=fmaxf(M1[3].y,w.y);
            }
        }
    };
    auto storeA = [&](uint32_t buf){
        #pragma unroll
        for (int h = 0; h < 2; h++){
            uint32_t r0h,r0l,r1h,r1l,r2h,r2l,r3h,r3l;
            split2(M0[h*2+0].x, M0[h*2+0].y, r0h, r0l);
            split2(M1[h*2+0].x, M1[h*2+0].y, r1h, r1l);
            split2(M0[h*2+1].x, M0[h*2+1].y, r2h, r2l);
            split2(M1[h*2+1].x, M1[h*2+1].y, r3h, r3l);
            uint32_t sb = buf*2048u + (uint32_t)((h*8 + fw)*128 + lane*4);
            *(uint4*)&Ah_s[sb] = make_uint4(r0h,r1h,r2h,r3h);
            *(uint4*)&Al_s[sb] = make_uint4(r0l,r1l,r2l,r3l);
        }
    };

    gather(0);
    storeA(0);
    __syncthreads();

    for (int c = 0; c < 8; c++){
        int buf = c & 1, nbuf = buf ^ 1;
        if (c+1 < 8) gather(c+1);
        uint32_t aoff = (uint32_t)buf*2048;
        #pragma unroll
        for (int h = 0; h < 2; h++){
            uint4 aH[2], aL[2];
            #pragma unroll
            for (int i = 0; i < 2; i++){
                uint32_t sb = aoff + (uint32_t)((h*8 + 2*mw + i)*128 + lane*4);
                aH[i] = *(const uint4*)&Ah_s[sb];
                aL[i] = *(const uint4*)&Al_s[sb];
            }
            int jj0 = nw*2;
            uint32_t base = (uint32_t)(c*1024 + (h*4 + jj0)*128 + lane*4);
            uint4 bH0 = *(const uint4*)&Bh_s[base];
            uint4 bH1 = *(const uint4*)&Bh_s[base + 128];
            uint4 bL0 = *(const uint4*)&Bl_s[base];
            uint4 bL1 = *(const uint4*)&Bl_s[base + 128];
            #pragma unroll
            for (int i = 0; i < 2; i++){
                mma3(acc[i][0], aH[i], aL[i], bH0.x, bH0.y, bL0.x, bL0.y);
                mma3(acc[i][1], aH[i], aL[i], bH0.z, bH0.w, bL0.z, bL0.w);
                mma3(acc[i][2], aH[i], aL[i], bH1.x, bH1.y, bL1.x, bL1.y);
                mma3(acc[i][3], aH[i], aL[i], bH1.z, bH1.w, bL1.z, bL1.w);
            }
        }
        if (c+1 < 8) storeA((uint32_t)nbuf);
        __syncthreads();
    }

    #pragma unroll
    for (int i = 0; i < 2; i++){
        #pragma unroll
        for (int j = 0; j < 4; j++){
            int cl = nw*32 + j*8 + 2*q;
            int r  = mw*32 + i*16 + gr;
            float m0 = (scnt[r]   > 0) ? 1.0f : 0.0f;
            float m1 = (scnt[r+8] > 0) ? 1.0f : 0.0f;
            float bx = bc[cl], by = bc[cl+1];
            float2 lo, hi;
            lo.x = fmaxf(acc[i][j][0] + bx, 0.0f)*m0;
            lo.y = fmaxf(acc[i][j][1] + by, 0.0f)*m0;
            hi.x = fmaxf(acc[i][j][2] + bx, 0.0f)*m1;
            hi.y = fmaxf(acc[i][j][3] + by, 0.0f)*m1;
            *(float2*)&g_comp[(size_t)(row0 + r)*64 + cl]     = lo;
            *(float2*)&g_comp[(size_t)(row0 + r + 8)*64 + cl] = hi;
        }
    }
}

__global__ __launch_bounds__(256) void residual_k(float* __restrict__ out){
    int idx = blockIdx.x*blockDim.x + threadIdx.x;
    const int TOT = BB*192*HH*WW;
    if (idx >= TOT) return;
    int w  = idx % WW;
    int h  = (idx / WW) % HH;
    int ch = (idx / (WW*HH)) % 192;
    int b  = idx / (WW*HH*192);
    int f = ch >> 6, j = ch & 63;
    int vl = ((b*FF + (FF-1))*HH + h)*WW + w;
    int vf = ((b*FF + f)*HH + h)*WW + w;
    out[idx] = g_comp[(size_t)vl*64 + j] - g_comp[(size_t)vf*64 + j];
}

extern "C" void kernel_launch(void* const* d_in, const int* in_sizes, int n_in,
                              void* d_out, int out_size){
    const float* pts   = (const float*)d_in[0];
    const int*   coors = (const int*)  d_in[1];
    const float* pre_g = (const float*)d_in[2];
    const float* pre_b = (const float*)d_in[3];
    const float* W1    = (const float*)d_in[4];
    const float* g1    = (const float*)d_in[5];
    const float* b1    = (const float*)d_in[6];
    const float* W2    = (const float*)d_in[7];
    const float* g2    = (const float*)d_in[8];
    const float* b2    = (const float*)d_in[9];
    const float* W3    = (const float*)d_in[10];
    const float* g3    = (const float*)d_in[11];
    const float* b3    = (const float*)d_in[12];
    const float* W4    = (const float*)d_in[13];
    const float* b4    = (const float*)d_in[14];
    const float* Wc    = (const float*)d_in[15];
    const float* bc    = (const float*)d_in[16];
    float* out = (float*)d_out;

    void *py1, *py2, *py3, *py4, *pstat;
    void *p2h,*p2l,*p3h,*p3l,*p4h,*p4l;
    cudaGetSymbolAddress(&py1, g_y1);
    cudaGetSymbolAddress(&py2, g_y2);
    cudaGetSymbolAddress(&py3, g_y3);
    cudaGetSymbolAddress(&py4, g_y4);
    cudaGetSymbolAddress(&pstat, g_stat);
    cudaGetSymbolAddress(&p2h, g_w2h); cudaGetSymbolAddress(&p2l, g_w2l);
    cudaGetSymbolAddress(&p3h, g_w3h); cudaGetSymbolAddress(&p3l, g_w3l);
    cudaGetSymbolAddress(&p4h, g_w4h); cudaGetSymbolAddress(&p4l, g_w4l);
    float* statb = (float*)pstat;

    const int SM_L2 = 32768 + 2*128*16*4 + 2*128*16*4 + 2*128*4;
    const int SM_L3 = 32768 + 2*256*16*4 + 4*256*16*4 + 2*256*4;
    const int SM_L4 = 32768 + 2*256*16*4 + 8*256*16*4 + 2*256*4;
    const int SM_COMP = 65536 + 32768 + 2*128*4;
    static bool attr_set = false;
    if (!attr_set){
        cudaFuncSetAttribute(mm_k<64,128,false,true>,  cudaFuncAttributeMaxDynamicSharedMemorySize, SM_L2);
        cudaFuncSetAttribute(mm_k<128,256,false,true>, cudaFuncAttributeMaxDynamicSharedMemorySize, SM_L3);
        cudaFuncSetAttribute(mm_k<256,256,true,false>, cudaFuncAttributeMaxDynamicSharedMemorySize, SM_L4);
        cudaFuncSetAttribute(comp_k, cudaFuncAttributeMaxDynamicSharedMemorySize, SM_COMP);
        attr_set = true;
    }

    init_k<<<1024, 256>>>();
    tr_all_k<<<240, 256>>>(W2, W3, W4, Wc);
    scatter_k<<<N_PTS/256, 256>>>(pts, coors);
    scan1_k<<<SS/1024, 1024>>>();
    scan2_k<<<1, 256>>>();
    scan3_k<<<SS/1024, 1024>>>();
    csrfeats_k<<<N_PTS/256, 256>>>(pts);
    bnparam_k<<<1, 256>>>(pre_g, pre_b, 8, 0);

    gemm1_k<<<N_PTS/128, 128>>>(W1);     // fused y1 stats
    bnparam_k<<<1, 256>>>(g1, b1, 64, 1);

    mm_k<64,128,false,true><<<N_PTS/128, 256, SM_L2>>>(
        (const float*)py1, (const uint32_t*)p2h, (const uint32_t*)p2l,
        (float*)py2, nullptr, 1, statb + 2*512);
    bnparam_k<<<1, 256>>>(g2, b2, 128, 2);

    mm_k<128,256,false,true><<<N_PTS/128, 256, SM_L3>>>(
        (const float*)py2, (const uint32_t*)p3h, (const uint32_t*)p3l,
        (float*)py3, nullptr, 2, statb + 3*512);
    bnparam_k<<<1, 256>>>(g3, b3, 256, 3);

    mm_k<256,256,true,false><<<N_PTS/128, 256, SM_L4>>>(
        (const float*)py3, (const uint32_t*)p4h, (const uint32_t*)p4l,
        (float*)py4, b4, 3, nullptr);

    comp_k<<<SS/128, 256, SM_COMP>>>(bc);

    const int TOT = BB*192*HH*WW;
    residual_k<<<(TOT + 255)/256, 256>>>(out);

    (void)in_sizes; (void)n_in; (void)out_size;
}